// round 9
// baseline (speedup 1.0000x reference)
#include <cuda_runtime.h>
#include <math.h>

#define BATCH   128
#define NITEMS  8192
#define HID     256
#define LAT     64
#define LEN1    4096
#define LEN2    8192
#define NEMB    512
#define NQ      4
#define MROWS   524288
#define VQBLOCKS 2048

typedef unsigned long long u64;

// ---------------- packed f32x2 primitives (per-lane exact IEEE fp32) ----
__device__ __forceinline__ u64 pk(float lo, float hi) {
    u64 r; asm("mov.b64 %0, {%1,%2};" : "=l"(r) : "f"(lo), "f"(hi)); return r;
}
__device__ __forceinline__ u64 pk2(float v) { return pk(v, v); }
__device__ __forceinline__ void upk(u64 a, float& lo, float& hi) {
    asm("mov.b64 {%0,%1}, %2;" : "=f"(lo), "=f"(hi) : "l"(a));
}
__device__ __forceinline__ u64 add2(u64 a, u64 b) {
    u64 r; asm("add.rn.f32x2 %0, %1, %2;" : "=l"(r) : "l"(a), "l"(b)); return r;
}
__device__ __forceinline__ u64 mul2(u64 a, u64 b) {
    u64 r; asm("mul.rn.f32x2 %0, %1, %2;" : "=l"(r) : "l"(a), "l"(b)); return r;
}
__device__ __forceinline__ u64 fma2(u64 a, u64 b, u64 c) {
    u64 r; asm("fma.rn.f32x2 %0, %1, %2, %3;" : "=l"(r) : "l"(a), "l"(b), "l"(c)); return r;
}
__device__ __forceinline__ u64 neg2(u64 a) { return a ^ 0x8000000080000000ULL; }
__device__ __forceinline__ u64 sub2(u64 a, u64 b) { return add2(a, neg2(b)); }  // IEEE a-b == a+(-b)

// packed double-float MAC: per-lane identical to scalar TwoProdFMA+TwoSum
#define DFMAC2(S, E, W, X) do {                                   \
    u64 _p  = mul2((W), (X));                                     \
    u64 _pe = fma2((W), (X), neg2(_p));                           \
    u64 _t  = add2((S), _p);                                      \
    u64 _z  = sub2(_t, (S));                                      \
    u64 _e1 = add2(sub2((S), sub2(_t, _z)), sub2(_p, _z));        \
    (S) = _t;                                                     \
    (E) = add2((E), add2(_e1, _pe));                              \
} while (0)

// ---------------- scratch ----------------
__device__ float g_bufA[268435456];
__device__ float g_bufB[268435456];
__device__ float g_res [33554432];
__device__ float g_zq  [33554432];
__device__ float g_dvec[BATCH * NITEMS];
__device__ float g_counts[NEMB];
__device__ float g_scal[2];
__device__ float g_bsums[VQBLOCKS];

// =================================================================
// encoder conv1 (fp64-exact, tiny)
// =================================================================
__global__ void __launch_bounds__(128) k_enc_conv1(
    const int* __restrict__ uid, const float* __restrict__ mat,
    const float* __restrict__ w, const float* __restrict__ bias,
    float* __restrict__ out)
{
    __shared__ float s_in[258];
    __shared__ float s_w[HID * 4];
    const int b  = blockIdx.y;
    const int l0 = blockIdx.x * 128;
    const int tx = threadIdx.x;
    const float* row = mat + (size_t)uid[b] * NITEMS;
    for (int i = tx; i < 258; i += 128) {
        int g = 2 * l0 - 1 + i;
        s_in[i] = (g >= 0 && g < NITEMS) ? row[g] : 0.f;
    }
    for (int i = tx; i < HID * 4; i += 128) s_w[i] = w[i];
    __syncthreads();
    const double x0 = s_in[2 * tx + 0], x1 = s_in[2 * tx + 1];
    const double x2 = s_in[2 * tx + 2], x3 = s_in[2 * tx + 3];
    const int l = l0 + tx;
    for (int co = 0; co < HID; co++) {
        double a = 0.0;
        a = fma((double)s_w[co * 4 + 0], x0, a);
        a = fma((double)s_w[co * 4 + 1], x1, a);
        a = fma((double)s_w[co * 4 + 2], x2, a);
        a = fma((double)s_w[co * 4 + 3], x3, a);
        float v = __fadd_rn((float)a, bias[co]);
        out[((size_t)b * HID + co) * LEN1 + l] = fmaxf(v, 0.f);
    }
}

// =================================================================
// encoder conv1d, packed double-float (bit-identical to R8 scalar df)
// tile 64co x 64l, 256 thr, per-thread 4co x 4l (= 4co x 2 packed jp)
// =================================================================
template <int K, bool RELU, bool ADDRES>
__global__ void __launch_bounds__(256) k_convdf(
    const float* __restrict__ in, const float* __restrict__ wt,
    const float* __restrict__ bias, const float* __restrict__ res,
    float* __restrict__ out, int CO, int CI, int L)
{
    constexpr int PAD = (K - 1) / 2;
    constexpr int LT = 64, COT = 64, CIC = 16;
    constexpr int LW = LT + 2 * PAD;
    __shared__ float s_in[CIC][LW];
    __shared__ float s_w[CIC][K][COT];

    const int b   = blockIdx.z;
    const int co0 = blockIdx.y * COT;
    const int l0  = blockIdx.x * LT;
    const int tid = threadIdx.x;
    const int lq = tid & 15, cq = tid >> 4;
    const int ls = lq * 4, cs = cq * 4;

    u64 as[4][2], ae[4][2];
#pragma unroll
    for (int i = 0; i < 4; i++)
#pragma unroll
        for (int jp = 0; jp < 2; jp++) { as[i][jp] = 0ULL; ae[i][jp] = 0ULL; }

    for (int ci0 = 0; ci0 < CI; ci0 += CIC) {
        for (int idx = tid; idx < CIC * LW; idx += 256) {
            int ci = idx / LW, x = idx % LW;
            int l = l0 - PAD + x;
            float v = 0.f;
            if (l >= 0 && l < L) v = in[((size_t)b * CI + ci0 + ci) * L + l];
            s_in[ci][x] = v;
        }
        for (int idx = tid; idx < CIC * K * COT; idx += 256) {
            int co = idx % COT;
            int k  = (idx / COT) % K;
            int ci = idx / (COT * K);
            s_w[ci][k][co] = wt[((size_t)(co0 + co) * CI + ci0 + ci) * K + k];
        }
        __syncthreads();
#pragma unroll 2
        for (int ci = 0; ci < CIC; ci++) {
            float x[4 + K - 1];
#pragma unroll
            for (int t = 0; t < 4 + K - 1; t++) x[t] = s_in[ci][ls + t];
            u64 xp[K][2];
#pragma unroll
            for (int k = 0; k < K; k++)
#pragma unroll
                for (int jp = 0; jp < 2; jp++)
                    xp[k][jp] = pk(x[k + 2 * jp], x[k + 2 * jp + 1]);
#pragma unroll
            for (int k = 0; k < K; k++) {
                float4 w4 = *reinterpret_cast<const float4*>(&s_w[ci][k][cs]);
                float wv[4] = {w4.x, w4.y, w4.z, w4.w};
#pragma unroll
                for (int i = 0; i < 4; i++) {
                    u64 wp = pk2(wv[i]);
                    DFMAC2(as[i][0], ae[i][0], wp, xp[k][0]);
                    DFMAC2(as[i][1], ae[i][1], wp, xp[k][1]);
                }
            }
        }
        __syncthreads();
    }
#pragma unroll
    for (int i = 0; i < 4; i++) {
        const int co = co0 + cs + i;
        const float bv = bias[co];
        const size_t o = ((size_t)b * CO + co) * L + l0 + ls;
        float v[4];
#pragma unroll
        for (int jp = 0; jp < 2; jp++) {
            u64 s2 = add2(as[i][jp], ae[i][jp]);   // per-lane fl(as+ae)
            float s0, s1; upk(s2, s0, s1);
            v[2 * jp + 0] = __fadd_rn(s0, bv);
            v[2 * jp + 1] = __fadd_rn(s1, bv);
        }
        if (ADDRES) {
            float4 r0 = *reinterpret_cast<const float4*>(&res[o]);
            v[0] = __fadd_rn(v[0], r0.x); v[1] = __fadd_rn(v[1], r0.y);
            v[2] = __fadd_rn(v[2], r0.z); v[3] = __fadd_rn(v[3], r0.w);
        }
        if (RELU) {
#pragma unroll
            for (int j = 0; j < 4; j++) v[j] = fmaxf(v[j], 0.f);
        }
        float4 o0 = {v[0], v[1], v[2], v[3]};
        *reinterpret_cast<float4*>(&out[o]) = o0;
    }
}

// =================================================================
// decoder conv1d fp32, packed (per-lane order identical to R8 scalar)
// =================================================================
template <int K, bool RELU, bool ADDRES>
__global__ void __launch_bounds__(256) k_conv(
    const float* __restrict__ in, const float* __restrict__ wt,
    const float* __restrict__ bias, const float* __restrict__ res,
    float* __restrict__ out, int CO, int CI, int L)
{
    constexpr int PAD = (K - 1) / 2;
    constexpr int LT = 128, COT = 64, CIC = 16;
    constexpr int LW = LT + 2 * PAD;
    __shared__ float s_in[CIC][LW];
    __shared__ float s_w[CIC][K][COT];

    const int b   = blockIdx.z;
    const int co0 = blockIdx.y * COT;
    const int l0  = blockIdx.x * LT;
    const int tid = threadIdx.x;
    const int lq = tid & 15, cq = tid >> 4;
    const int ls = lq * 8, cs = cq * 4;

    u64 acc[4][4];
#pragma unroll
    for (int i = 0; i < 4; i++)
#pragma unroll
        for (int jp = 0; jp < 4; jp++) acc[i][jp] = 0ULL;

    for (int ci0 = 0; ci0 < CI; ci0 += CIC) {
        for (int idx = tid; idx < CIC * LW; idx += 256) {
            int ci = idx / LW, x = idx % LW;
            int l = l0 - PAD + x;
            float v = 0.f;
            if (l >= 0 && l < L) v = in[((size_t)b * CI + ci0 + ci) * L + l];
            s_in[ci][x] = v;
        }
        for (int idx = tid; idx < CIC * K * COT; idx += 256) {
            int co = idx % COT;
            int k  = (idx / COT) % K;
            int ci = idx / (COT * K);
            s_w[ci][k][co] = wt[((size_t)(co0 + co) * CI + ci0 + ci) * K + k];
        }
        __syncthreads();
#pragma unroll 4
        for (int ci = 0; ci < CIC; ci++) {
            float x[8 + K - 1];
#pragma unroll
            for (int t = 0; t < 8 + K - 1; t++) x[t] = s_in[ci][ls + t];
            u64 xp[K][4];
#pragma unroll
            for (int k = 0; k < K; k++)
#pragma unroll
                for (int jp = 0; jp < 4; jp++)
                    xp[k][jp] = pk(x[k + 2 * jp], x[k + 2 * jp + 1]);
#pragma unroll
            for (int k = 0; k < K; k++) {
                float4 w4 = *reinterpret_cast<const float4*>(&s_w[ci][k][cs]);
                float wv[4] = {w4.x, w4.y, w4.z, w4.w};
#pragma unroll
                for (int i = 0; i < 4; i++) {
                    u64 wp = pk2(wv[i]);
#pragma unroll
                    for (int jp = 0; jp < 4; jp++)
                        acc[i][jp] = fma2(wp, xp[k][jp], acc[i][jp]);
                }
            }
        }
        __syncthreads();
    }
#pragma unroll
    for (int i = 0; i < 4; i++) {
        const int co = co0 + cs + i;
        const float bv = bias[co];
        const size_t o = ((size_t)b * CO + co) * L + l0 + ls;
        float v[8];
#pragma unroll
        for (int jp = 0; jp < 4; jp++) {
            float a0, a1; upk(acc[i][jp], a0, a1);
            v[2 * jp + 0] = __fadd_rn(a0, bv);
            v[2 * jp + 1] = __fadd_rn(a1, bv);
        }
        if (ADDRES) {
            float4 r0 = *reinterpret_cast<const float4*>(&res[o]);
            float4 r1 = *reinterpret_cast<const float4*>(&res[o + 4]);
            v[0] = __fadd_rn(v[0], r0.x); v[1] = __fadd_rn(v[1], r0.y);
            v[2] = __fadd_rn(v[2], r0.z); v[3] = __fadd_rn(v[3], r0.w);
            v[4] = __fadd_rn(v[4], r1.x); v[5] = __fadd_rn(v[5], r1.y);
            v[6] = __fadd_rn(v[6], r1.z); v[7] = __fadd_rn(v[7], r1.w);
        }
        if (RELU) {
#pragma unroll
            for (int j = 0; j < 8; j++) v[j] = fmaxf(v[j], 0.f);
        }
        float4 o0 = {v[0], v[1], v[2], v[3]};
        float4 o1 = {v[4], v[5], v[6], v[7]};
        *reinterpret_cast<float4*>(&out[o])     = o0;
        *reinterpret_cast<float4*>(&out[o + 4]) = o1;
    }
}

// =================================================================
// VQ: packed fp32 screen (provable margin) + exact fp64 refine
// =================================================================
union RowU {
    float f[64];
    u64 p[32];
    ulonglong2 q[16];
};

__device__ __forceinline__ float keydot(const float* crow, const RowU& r) {
    const ulonglong2* cu = reinterpret_cast<const ulonglong2*>(crow);
    u64 acc = 0ULL;
#pragma unroll
    for (int t = 0; t < 16; t++) {
        ulonglong2 c2 = cu[t];
        acc = fma2(c2.x, r.p[2 * t + 0], acc);
        acc = fma2(c2.y, r.p[2 * t + 1], acc);
    }
    float lo, hi; upk(acc, lo, hi);
    return __fadd_rn(lo, hi);
}

__global__ void __launch_bounds__(256) k_vq(
    const float* __restrict__ cb, float* __restrict__ resid,
    float* __restrict__ zq, float* __restrict__ counts,
    float* __restrict__ bsums)
{
    extern __shared__ float sm[];
    float* s_code = sm;               // 512*64 codes (fp32)
    float* s_cn   = sm + NEMB * LAT;  // fl32(exact norm)
    const int tid = threadIdx.x;

    for (int idx = tid; idx < NEMB * LAT / 4; idx += 256)
        reinterpret_cast<float4*>(s_code)[idx] =
            reinterpret_cast<const float4*>(cb)[idx];
    __syncthreads();
    for (int e = tid; e < NEMB; e += 256) {
        const float* c = s_code + e * LAT;
        double s = 0.0;
#pragma unroll
        for (int j = 0; j < 64; j++) s = fma((double)c[j], (double)c[j], s);
        s_cn[e] = (float)s;
    }
    __syncthreads();

    const size_t m = (size_t)blockIdx.x * 256 + tid;
    RowU r;
    {
        const ulonglong2* g = reinterpret_cast<const ulonglong2*>(resid + m * 64);
#pragma unroll
        for (int t = 0; t < 16; t++) r.q[t] = g[t];
    }
    double rn64 = 0.0;
#pragma unroll
    for (int j = 0; j < 64; j++)
        rn64 = fma((double)r.f[j], (double)r.f[j], rn64);
    const float rn = (float)rn64;

    float sabs = 0.f;
#pragma unroll
    for (int j = 0; j < 64; j++) sabs = __fadd_rn(sabs, fabsf(r.f[j]));

    // ---- stage A: packed fp32 approx keys, find min ----
    float best_ka = 3.4e38f;
    for (int e = 0; e < NEMB; e += 2) {
        float d0 = keydot(s_code + (e + 0) * LAT, r);
        float d1 = keydot(s_code + (e + 1) * LAT, r);
        float ka0 = __fsub_rn(__fadd_rn(rn, s_cn[e + 0]), __fmul_rn(2.f, d0));
        float ka1 = __fsub_rn(__fadd_rn(rn, s_cn[e + 1]), __fmul_rn(2.f, d1));
        best_ka = fminf(best_ka, fminf(ka0, ka1));
    }

    const float margin = 4.8e-7f * rn + 6.4e-8f * sabs + 1e-8f;
    const float thr = best_ka + margin;

    // ---- stage B: identical packed keys re-screen + exact fp64 refine ----
    float best = 3.4e38f;
    int bi = 0;
    for (int e = 0; e < NEMB; e += 2) {
        float d0 = keydot(s_code + (e + 0) * LAT, r);
        float d1 = keydot(s_code + (e + 1) * LAT, r);
        float ka[2];
        ka[0] = __fsub_rn(__fadd_rn(rn, s_cn[e + 0]), __fmul_rn(2.f, d0));
        ka[1] = __fsub_rn(__fadd_rn(rn, s_cn[e + 1]), __fmul_rn(2.f, d1));
#pragma unroll
        for (int i = 0; i < 2; i++) {
            if (ka[i] <= thr) {
                const float* c = s_code + (size_t)(e + i) * LAT;
                double dd = 0.0;
#pragma unroll
                for (int j = 0; j < 64; j++)
                    dd = fma((double)c[j], (double)r.f[j], dd);
                float dot = (float)dd;
                float dist = __fsub_rn(__fadd_rn(rn, s_cn[e + i]),
                                       __fmul_rn(2.f, dot));
                if (dist < best) { best = dist; bi = e + i; }
            }
        }
    }

    // straight-through update (exact fp32, unchanged bit-path)
    float sq = 0.f;
    {
        const float* c = s_code + bi * LAT;
        float4* rg = reinterpret_cast<float4*>(resid + m * 64);
        float4* zg = reinterpret_cast<float4*>(zq + m * 64);
#pragma unroll
        for (int t = 0; t < 16; t++) {
            float4 zv = zg[t];
            float q[4] = {c[t*4+0], c[t*4+1], c[t*4+2], c[t*4+3]};
            float rv[4] = {r.f[t*4+0], r.f[t*4+1], r.f[t*4+2], r.f[t*4+3]};
            float4 nr, nz;
            float o_r[4], o_z[4];
#pragma unroll
            for (int u = 0; u < 4; u++) {
                float d  = __fsub_rn(q[u], rv[u]);
                sq = __fadd_rn(sq, __fmul_rn(d, d));
                float qs = __fadd_rn(rv[u], d);
                o_r[u] = __fsub_rn(rv[u], qs);
                o_z[u] = __fadd_rn((&zv.x)[u], qs);
            }
            nr.x = o_r[0]; nr.y = o_r[1]; nr.z = o_r[2]; nr.w = o_r[3];
            nz.x = o_z[0]; nz.y = o_z[1]; nz.z = o_z[2]; nz.w = o_z[3];
            rg[t] = nr; zg[t] = nz;
        }
    }
    atomicAdd(&counts[bi], 1.f);

    __shared__ float red[256];
    red[tid] = sq;
    __syncthreads();
    for (int s = 128; s > 0; s >>= 1) {
        if (tid < s) red[tid] += red[tid + s];
        __syncthreads();
    }
    if (tid == 0) bsums[blockIdx.x] = red[0];
}

__global__ void k_perp(const float* __restrict__ bsums, float* __restrict__ counts,
                       float* __restrict__ scal)
{
    __shared__ float red[512];
    __shared__ float red2[512];
    const int t = threadIdx.x;
    float c = counts[t];
    float avg = c * (1.0f / (float)MROWS);
    red[t] = avg * logf(avg + 1e-10f);
    float s2 = 0.f;
    for (int i = t; i < VQBLOCKS; i += 512) s2 += bsums[i];
    red2[t] = s2;
    __syncthreads();
    for (int s = 256; s > 0; s >>= 1) {
        if (t < s) { red[t] += red[t + s]; red2[t] += red2[t + s]; }
        __syncthreads();
    }
    if (t == 0) {
        scal[1] += expf(-red[0]);
        scal[0] += red2[0];
    }
    counts[t] = 0.f;
}

// =================================================================
// decoder ConvTranspose1d(64->256, K=4, s2, p1) + relu, packed fp32
// =================================================================
__global__ void __launch_bounds__(256) k_dect(
    const float* __restrict__ in, const float* __restrict__ wt,
    const float* __restrict__ bias, float* __restrict__ out)
{
    constexpr int OT = 128, COT = 64, CIC = 32;
    __shared__ float s_in[CIC][66];
    __shared__ float s_w[CIC][4][COT];
    const int b   = blockIdx.z;
    const int co0 = blockIdx.y * COT;
    const int o0  = blockIdx.x * OT;
    const int tid = threadIdx.x;
    const int lq = tid & 15, cq = tid >> 4;
    const int os = lq * 8, cs = cq * 4;
    const int lbase = o0 / 2 - 1;

    u64 acc[4][4];
#pragma unroll
    for (int i = 0; i < 4; i++)
#pragma unroll
        for (int jj = 0; jj < 4; jj++) acc[i][jj] = 0ULL;

    for (int ci0 = 0; ci0 < LAT; ci0 += CIC) {
        for (int idx = tid; idx < CIC * 66; idx += 256) {
            int ci = idx / 66, x = idx % 66;
            int l = lbase + x;
            float v = 0.f;
            if (l >= 0 && l < LEN1) v = in[((size_t)b * LAT + ci0 + ci) * LEN1 + l];
            s_in[ci][x] = v;
        }
        for (int idx = tid; idx < CIC * 4 * COT; idx += 256) {
            int co = idx & 63;
            int k  = (idx >> 6) & 3;
            int ci = idx >> 8;
            s_w[ci][k][co] = wt[((size_t)(ci0 + ci) * HID + co0 + co) * 4 + k];
        }
        __syncthreads();
#pragma unroll 4
        for (int ci = 0; ci < CIC; ci++) {
            float x[6];
#pragma unroll
            for (int t = 0; t < 6; t++) x[t] = s_in[ci][(os >> 1) + t];
            u64 X0[4], X1[4];
#pragma unroll
            for (int jj = 0; jj < 4; jj++) {
                X0[jj] = pk(x[jj],     x[jj + 1]);   // (xe0 | xe1)
                X1[jj] = pk(x[jj + 1], x[jj + 2]);   // (xe1 | xo2)
            }
            float4 W0 = *reinterpret_cast<const float4*>(&s_w[ci][0][cs]);
            float4 W1 = *reinterpret_cast<const float4*>(&s_w[ci][1][cs]);
            float4 W2 = *reinterpret_cast<const float4*>(&s_w[ci][2][cs]);
            float4 W3 = *reinterpret_cast<const float4*>(&s_w[ci][3][cs]);
            float wa[4][4] = {{W0.x, W0.y, W0.z, W0.w},
                              {W1.x, W1.y, W1.z, W1.w},
                              {W2.x, W2.y, W2.z, W2.w},
                              {W3.x, W3.y, W3.z, W3.w}};
#pragma unroll
            for (int i = 0; i < 4; i++) {
                u64 wp10 = pk(wa[1][i], wa[0][i]);
                u64 wp32 = pk(wa[3][i], wa[2][i]);
#pragma unroll
                for (int jj = 0; jj < 4; jj++)
                    acc[i][jj] = fma2(wp10, X1[jj], fma2(wp32, X0[jj], acc[i][jj]));
            }
        }
        __syncthreads();
    }
#pragma unroll
    for (int i = 0; i < 4; i++) {
        const int co = co0 + cs + i;
        const float bv = bias[co];
        const size_t o = ((size_t)b * HID + co) * LEN2 + o0 + os;
        float v[8];
#pragma unroll
        for (int jj = 0; jj < 4; jj++) {
            float a0, a1; upk(acc[i][jj], a0, a1);
            v[2 * jj + 0] = fmaxf(__fadd_rn(a0, bv), 0.f);
            v[2 * jj + 1] = fmaxf(__fadd_rn(a1, bv), 0.f);
        }
        float4 q0 = {v[0], v[1], v[2], v[3]};
        float4 q1 = {v[4], v[5], v[6], v[7]};
        *reinterpret_cast<float4*>(&out[o])     = q0;
        *reinterpret_cast<float4*>(&out[o + 4]) = q1;
    }
}

// =================================================================
// decoder ConvTranspose1d(256->1, K=3, s1, p1) (fp32 scalar, tiny)
// =================================================================
__global__ void __launch_bounds__(256) k_decfinal(
    const float* __restrict__ in, const float* __restrict__ wt,
    const float* __restrict__ bias, float* __restrict__ out)
{
    __shared__ float s_w[HID * 3];
    __shared__ float s_in[32][258];
    const int b  = blockIdx.y;
    const int o0 = blockIdx.x * 256;
    const int tx = threadIdx.x;
    for (int i = tx; i < HID * 3; i += 256) s_w[i] = wt[i];
    float acc = 0.f;
    for (int cc = 0; cc < HID; cc += 32) {
        __syncthreads();
        for (int idx = tx; idx < 32 * 258; idx += 256) {
            int ci = idx / 258, x = idx % 258;
            int l = o0 - 1 + x;
            s_in[ci][x] = (l >= 0 && l < LEN2)
                        ? in[((size_t)b * HID + cc + ci) * LEN2 + l] : 0.f;
        }
        __syncthreads();
#pragma unroll 8
        for (int ci = 0; ci < 32; ci++) {
            acc = fmaf(s_w[(cc + ci) * 3 + 0], s_in[ci][tx + 2], acc);
            acc = fmaf(s_w[(cc + ci) * 3 + 1], s_in[ci][tx + 1], acc);
            acc = fmaf(s_w[(cc + ci) * 3 + 2], s_in[ci][tx + 0], acc);
        }
    }
    out[(size_t)b * LEN2 + o0 + tx] = __fadd_rn(acc, bias[0]);
}

// =================================================================
// out projection, packed fp32 (per-lane order identical to scalar)
// =================================================================
__global__ void __launch_bounds__(256) k_outproj(
    const float* __restrict__ dv, const float* __restrict__ W,
    const float* __restrict__ bias, float* __restrict__ out)
{
    constexpr int KC = 32;
    __shared__ float s_d[KC][136];
    __shared__ float s_w[KC][68];
    const int j0  = blockIdx.x * 64;
    const int tid = threadIdx.x;
    const int bq = tid & 15, jq = tid >> 4;
    const int bs = bq * 8, js = jq * 4;
    u64 acc[8][2];
#pragma unroll
    for (int i = 0; i < 8; i++) { acc[i][0] = 0ULL; acc[i][1] = 0ULL; }

    for (int k0 = 0; k0 < NITEMS; k0 += KC) {
        for (int idx = tid; idx < KC * 128; idx += 256) {
            int bb = idx >> 5, k = idx & 31;
            s_d[k][bb] = dv[(size_t)bb * NITEMS + k0 + k];
        }
        for (int idx = tid; idx < KC * 64; idx += 256) {
            int j = idx >> 5, k = idx & 31;
            s_w[k][j] = W[(size_t)(j0 + j) * NITEMS + k0 + k];
        }
        __syncthreads();
#pragma unroll
        for (int k = 0; k < KC; k++) {
            float4 w4 = *reinterpret_cast<const float4*>(&s_w[k][js]);
            u64 w01 = pk(w4.x, w4.y);
            u64 w23 = pk(w4.z, w4.w);
            float xb[8];
            *reinterpret_cast<float4*>(&xb[0]) = *reinterpret_cast<const float4*>(&s_d[k][bs]);
            *reinterpret_cast<float4*>(&xb[4]) = *reinterpret_cast<const float4*>(&s_d[k][bs + 4]);
#pragma unroll
            for (int i = 0; i < 8; i++) {
                u64 xp = pk2(xb[i]);
                acc[i][0] = fma2(xp, w01, acc[i][0]);
                acc[i][1] = fma2(xp, w23, acc[i][1]);
            }
        }
        __syncthreads();
    }
#pragma unroll
    for (int i = 0; i < 8; i++) {
        float a0, a1, a2, a3;
        upk(acc[i][0], a0, a1);
        upk(acc[i][1], a2, a3);
        const size_t o = (size_t)(bs + i) * NITEMS + j0 + js;
        out[o + 0] = __fadd_rn(a0, bias[j0 + js + 0]);
        out[o + 1] = __fadd_rn(a1, bias[j0 + js + 1]);
        out[o + 2] = __fadd_rn(a2, bias[j0 + js + 2]);
        out[o + 3] = __fadd_rn(a3, bias[j0 + js + 3]);
    }
}

__global__ void k_final(const float* __restrict__ scal, float* __restrict__ out, int out_size)
{
    if (out_size >= BATCH * NITEMS + 2) {
        out[BATCH * NITEMS + 0] = 1.25f * scal[0] * (1.0f / 33554432.0f);
        out[BATCH * NITEMS + 1] = scal[1] * 0.25f;
    }
}

// =================================================================
extern "C" void kernel_launch(void* const* d_in, const int* in_sizes, int n_in,
                              void* d_out, int out_size)
{
    const int*   uid  = (const int*)  d_in[0];
    const float* mat  = (const float*)d_in[1];
    const float* ecw  = (const float*)d_in[2];
    const float* ecb  = (const float*)d_in[3];
    const float* erw1 = (const float*)d_in[4];
    const float* erb1 = (const float*)d_in[5];
    const float* erw2 = (const float*)d_in[6];
    const float* erb2 = (const float*)d_in[7];
    const float* efw  = (const float*)d_in[8];
    const float* efb  = (const float*)d_in[9];
    const float* cbs  = (const float*)d_in[10];
    const float* dtw  = (const float*)d_in[11];
    const float* dtb  = (const float*)d_in[12];
    const float* drw1 = (const float*)d_in[13];
    const float* drb1 = (const float*)d_in[14];
    const float* drw2 = (const float*)d_in[15];
    const float* drb2 = (const float*)d_in[16];
    const float* dfw  = (const float*)d_in[17];
    const float* dfb  = (const float*)d_in[18];
    const float* opw  = (const float*)d_in[19];
    const float* opb  = (const float*)d_in[20];
    float* out = (float*)d_out;

    float *bufA, *bufB, *resid, *zq, *dvec, *counts, *scal, *bsums;
    cudaGetSymbolAddress((void**)&bufA,   g_bufA);
    cudaGetSymbolAddress((void**)&bufB,   g_bufB);
    cudaGetSymbolAddress((void**)&resid,  g_res);
    cudaGetSymbolAddress((void**)&zq,     g_zq);
    cudaGetSymbolAddress((void**)&dvec,   g_dvec);
    cudaGetSymbolAddress((void**)&counts, g_counts);
    cudaGetSymbolAddress((void**)&scal,   g_scal);
    cudaGetSymbolAddress((void**)&bsums,  g_bsums);

    const int vq_smem = (NEMB * LAT + NEMB) * (int)sizeof(float);
    cudaFuncSetAttribute(k_vq, cudaFuncAttributeMaxDynamicSharedMemorySize, vq_smem);

    cudaMemsetAsync(zq, 0, (size_t)33554432 * sizeof(float), 0);
    cudaMemsetAsync(scal, 0, 2 * sizeof(float), 0);
    cudaMemsetAsync(counts, 0, NEMB * sizeof(float), 0);

    // ---------------- encoder (packed double-float exact) ----------------
    k_enc_conv1<<<dim3(LEN1 / 128, BATCH), 128>>>(uid, mat, ecw, ecb, bufA);
    for (int i = 0; i < 2; i++) {
        k_convdf<3, true, false><<<dim3(LEN1 / 64, HID / 64, BATCH), 256>>>(
            bufA, erw1 + (size_t)i * HID * HID * 3, erb1 + i * HID, nullptr, bufB,
            HID, HID, LEN1);
        k_convdf<1, true, true><<<dim3(LEN1 / 64, HID / 64, BATCH), 256>>>(
            bufB, erw2 + (size_t)i * HID * HID, erb2 + i * HID, bufA, bufA,
            HID, HID, LEN1);
    }
    k_convdf<3, false, false><<<dim3(LEN1 / 64, 1, BATCH), 256>>>(
        bufA, efw, efb, nullptr, resid, LAT, HID, LEN1);

    // ---------------- residual VQ (packed screen + exact refine) --------
    for (int q = 0; q < NQ; q++) {
        k_vq<<<VQBLOCKS, 256, vq_smem>>>(cbs + (size_t)q * NEMB * LAT,
                                         resid, zq, counts, bsums);
        k_perp<<<1, 512>>>(bsums, counts, scal);
    }

    // ---------------- decoder (packed fp32) ----------------
    k_dect<<<dim3(LEN2 / 128, HID / 64, BATCH), 256>>>(zq, dtw, dtb, bufA);
    for (int i = 0; i < 2; i++) {
        k_conv<3, true, false><<<dim3(LEN2 / 128, HID / 64, BATCH), 256>>>(
            bufA, drw1 + (size_t)i * HID * HID * 3, drb1 + i * HID, nullptr, bufB,
            HID, HID, LEN2);
        k_conv<1, true, true><<<dim3(LEN2 / 128, HID / 64, BATCH), 256>>>(
            bufB, drw2 + (size_t)i * HID * HID, drb2 + i * HID, bufA, bufA,
            HID, HID, LEN2);
    }
    k_decfinal<<<dim3(LEN2 / 256, BATCH), 256>>>(bufA, dfw, dfb, dvec);

    // ---------------- output projection + scalars ----------------
    k_outproj<<<NITEMS / 64, 256>>>(dvec, opw, opb, out);
    k_final<<<1, 1>>>(scal, out, out_size);
}

// round 10
// speedup vs baseline: 1.0185x; 1.0185x over previous
#include <cuda_runtime.h>
#include <math.h>

#define BATCH   128
#define NITEMS  8192
#define HID     256
#define LAT     64
#define LEN1    4096
#define LEN2    8192
#define NEMB    512
#define NQ      4
#define MROWS   524288
#define VQBLOCKS 2048

// ---------------- scratch ----------------
__device__ float g_bufA[268435456];
__device__ float g_bufB[268435456];
__device__ float g_res [33554432];
__device__ float g_zq  [33554432];
__device__ float g_dvec[BATCH * NITEMS];
__device__ float g_counts[NEMB];
__device__ float g_scal[2];
__device__ float g_bsums[VQBLOCKS];

// Double-float MAC: error-free product (TwoProdFMA) + error-free sum
// (TwoSum). (s+e) tracks the exact sum to ~2^-47 relative.
#define DFMAC(S, E, W, X) do {                                   \
    float _p  = __fmul_rn((W), (X));                             \
    float _pe = __fmaf_rn((W), (X), -_p);                        \
    float _t  = __fadd_rn((S), _p);                              \
    float _z  = __fsub_rn(_t, (S));                              \
    float _e1 = __fadd_rn(__fsub_rn((S), __fsub_rn(_t, _z)),     \
                          __fsub_rn(_p, _z));                    \
    (S) = _t;                                                    \
    (E) = __fadd_rn((E), __fadd_rn(_e1, _pe));                   \
} while (0)

// =================================================================
// encoder conv1 (fp64-exact, tiny)
// =================================================================
__global__ void __launch_bounds__(128) k_enc_conv1(
    const int* __restrict__ uid, const float* __restrict__ mat,
    const float* __restrict__ w, const float* __restrict__ bias,
    float* __restrict__ out)
{
    __shared__ float s_in[258];
    __shared__ float s_w[HID * 4];
    const int b  = blockIdx.y;
    const int l0 = blockIdx.x * 128;
    const int tx = threadIdx.x;
    const float* row = mat + (size_t)uid[b] * NITEMS;
    for (int i = tx; i < 258; i += 128) {
        int g = 2 * l0 - 1 + i;
        s_in[i] = (g >= 0 && g < NITEMS) ? row[g] : 0.f;
    }
    for (int i = tx; i < HID * 4; i += 128) s_w[i] = w[i];
    __syncthreads();
    const double x0 = s_in[2 * tx + 0], x1 = s_in[2 * tx + 1];
    const double x2 = s_in[2 * tx + 2], x3 = s_in[2 * tx + 3];
    const int l = l0 + tx;
    for (int co = 0; co < HID; co++) {
        double a = 0.0;
        a = fma((double)s_w[co * 4 + 0], x0, a);
        a = fma((double)s_w[co * 4 + 1], x1, a);
        a = fma((double)s_w[co * 4 + 2], x2, a);
        a = fma((double)s_w[co * 4 + 3], x3, a);
        float v = __fadd_rn((float)a, bias[co]);
        out[((size_t)b * HID + co) * LEN1 + l] = fmaxf(v, 0.f);
    }
}

// =================================================================
// encoder conv1d, double-float accumulate (bit-identical per-output
// (ci,k) order to R8). Tile 128co x 64l, 256 thr, per-thread 8co x 4l.
// =================================================================
template <int K, bool RELU, bool ADDRES>
__global__ void __launch_bounds__(256) k_convdf(
    const float* __restrict__ in, const float* __restrict__ wt,
    const float* __restrict__ bias, const float* __restrict__ res,
    float* __restrict__ out, int CO, int CI, int L)
{
    constexpr int PAD = (K - 1) / 2;
    constexpr int LT = 64, COT = 128, CIC = 16;
    constexpr int LW = LT + 2 * PAD;
    __shared__ float s_in[CIC][LW];
    __shared__ float s_w[CIC][K][COT];

    const int b   = blockIdx.z;
    const int co0 = blockIdx.y * COT;
    const int l0  = blockIdx.x * LT;
    const int tid = threadIdx.x;
    const int lq = tid & 15, cq = tid >> 4;
    const int ls = lq * 4, cs = cq * 8;

    float as[8][4], ae[8][4];
#pragma unroll
    for (int i = 0; i < 8; i++)
#pragma unroll
        for (int j = 0; j < 4; j++) { as[i][j] = 0.f; ae[i][j] = 0.f; }

    for (int ci0 = 0; ci0 < CI; ci0 += CIC) {
        for (int idx = tid; idx < CIC * LW; idx += 256) {
            int ci = idx / LW, x = idx % LW;
            int l = l0 - PAD + x;
            float v = 0.f;
            if (l >= 0 && l < L) v = in[((size_t)b * CI + ci0 + ci) * L + l];
            s_in[ci][x] = v;
        }
        for (int idx = tid; idx < CIC * K * COT; idx += 256) {
            int co = idx % COT;
            int k  = (idx / COT) % K;
            int ci = idx / (COT * K);
            s_w[ci][k][co] = wt[((size_t)(co0 + co) * CI + ci0 + ci) * K + k];
        }
        __syncthreads();
#pragma unroll 2
        for (int ci = 0; ci < CIC; ci++) {
            float x[4 + K - 1];
#pragma unroll
            for (int t = 0; t < 4 + K - 1; t++) x[t] = s_in[ci][ls + t];
#pragma unroll
            for (int k = 0; k < K; k++) {
                float4 wa = *reinterpret_cast<const float4*>(&s_w[ci][k][cs]);
                float4 wb = *reinterpret_cast<const float4*>(&s_w[ci][k][cs + 4]);
                float wv[8] = {wa.x, wa.y, wa.z, wa.w, wb.x, wb.y, wb.z, wb.w};
#pragma unroll
                for (int i = 0; i < 8; i++)
#pragma unroll
                    for (int j = 0; j < 4; j++)
                        DFMAC(as[i][j], ae[i][j], wv[i], x[j + k]);
            }
        }
        __syncthreads();
    }
#pragma unroll
    for (int i = 0; i < 8; i++) {
        const int co = co0 + cs + i;
        const float bv = bias[co];
        const size_t o = ((size_t)b * CO + co) * L + l0 + ls;
        float v[4];
#pragma unroll
        for (int j = 0; j < 4; j++)
            v[j] = __fadd_rn(__fadd_rn(as[i][j], ae[i][j]), bv);
        if (ADDRES) {
            float4 r0 = *reinterpret_cast<const float4*>(&res[o]);
            v[0] = __fadd_rn(v[0], r0.x); v[1] = __fadd_rn(v[1], r0.y);
            v[2] = __fadd_rn(v[2], r0.z); v[3] = __fadd_rn(v[3], r0.w);
        }
        if (RELU) {
#pragma unroll
            for (int j = 0; j < 4; j++) v[j] = fmaxf(v[j], 0.f);
        }
        float4 o0 = {v[0], v[1], v[2], v[3]};
        *reinterpret_cast<float4*>(&out[o]) = o0;
    }
}

// enc_final: CO=64 < COT=128 — dedicated narrow version (4co x 4l)
template <int K>
__global__ void __launch_bounds__(256) k_convdf_narrow(
    const float* __restrict__ in, const float* __restrict__ wt,
    const float* __restrict__ bias, float* __restrict__ out,
    int CO, int CI, int L)
{
    constexpr int PAD = (K - 1) / 2;
    constexpr int LT = 64, COT = 64, CIC = 16;
    constexpr int LW = LT + 2 * PAD;
    __shared__ float s_in[CIC][LW];
    __shared__ float s_w[CIC][K][COT];

    const int b   = blockIdx.z;
    const int co0 = blockIdx.y * COT;
    const int l0  = blockIdx.x * LT;
    const int tid = threadIdx.x;
    const int lq = tid & 15, cq = tid >> 4;
    const int ls = lq * 4, cs = cq * 4;

    float as[4][4], ae[4][4];
#pragma unroll
    for (int i = 0; i < 4; i++)
#pragma unroll
        for (int j = 0; j < 4; j++) { as[i][j] = 0.f; ae[i][j] = 0.f; }

    for (int ci0 = 0; ci0 < CI; ci0 += CIC) {
        for (int idx = tid; idx < CIC * LW; idx += 256) {
            int ci = idx / LW, x = idx % LW;
            int l = l0 - PAD + x;
            float v = 0.f;
            if (l >= 0 && l < L) v = in[((size_t)b * CI + ci0 + ci) * L + l];
            s_in[ci][x] = v;
        }
        for (int idx = tid; idx < CIC * K * COT; idx += 256) {
            int co = idx % COT;
            int k  = (idx / COT) % K;
            int ci = idx / (COT * K);
            s_w[ci][k][co] = wt[((size_t)(co0 + co) * CI + ci0 + ci) * K + k];
        }
        __syncthreads();
#pragma unroll 2
        for (int ci = 0; ci < CIC; ci++) {
            float x[4 + K - 1];
#pragma unroll
            for (int t = 0; t < 4 + K - 1; t++) x[t] = s_in[ci][ls + t];
#pragma unroll
            for (int k = 0; k < K; k++) {
                float4 w4 = *reinterpret_cast<const float4*>(&s_w[ci][k][cs]);
                float wv[4] = {w4.x, w4.y, w4.z, w4.w};
#pragma unroll
                for (int i = 0; i < 4; i++)
#pragma unroll
                    for (int j = 0; j < 4; j++)
                        DFMAC(as[i][j], ae[i][j], wv[i], x[j + k]);
            }
        }
        __syncthreads();
    }
#pragma unroll
    for (int i = 0; i < 4; i++) {
        const int co = co0 + cs + i;
        const float bv = bias[co];
        const size_t o = ((size_t)b * CO + co) * L + l0 + ls;
        float v[4];
#pragma unroll
        for (int j = 0; j < 4; j++)
            v[j] = __fadd_rn(__fadd_rn(as[i][j], ae[i][j]), bv);
        float4 o0 = {v[0], v[1], v[2], v[3]};
        *reinterpret_cast<float4*>(&out[o]) = o0;
    }
}

// =================================================================
// decoder conv1d (fp32 scalar, R8 version), K in {1,3}
// =================================================================
template <int K, bool RELU, bool ADDRES>
__global__ void __launch_bounds__(256) k_conv(
    const float* __restrict__ in, const float* __restrict__ wt,
    const float* __restrict__ bias, const float* __restrict__ res,
    float* __restrict__ out, int CO, int CI, int L)
{
    constexpr int PAD = (K - 1) / 2;
    constexpr int LT = 128, COT = 64, CIC = 16;
    constexpr int LW = LT + 2 * PAD;
    __shared__ float s_in[CIC][LW];
    __shared__ float s_w[CIC][K][COT];

    const int b   = blockIdx.z;
    const int co0 = blockIdx.y * COT;
    const int l0  = blockIdx.x * LT;
    const int tid = threadIdx.x;
    const int lq = tid & 15, cq = tid >> 4;
    const int ls = lq * 8, cs = cq * 4;

    float acc[4][8];
#pragma unroll
    for (int i = 0; i < 4; i++)
#pragma unroll
        for (int j = 0; j < 8; j++) acc[i][j] = 0.f;

    for (int ci0 = 0; ci0 < CI; ci0 += CIC) {
        for (int idx = tid; idx < CIC * LW; idx += 256) {
            int ci = idx / LW, x = idx % LW;
            int l = l0 - PAD + x;
            float v = 0.f;
            if (l >= 0 && l < L) v = in[((size_t)b * CI + ci0 + ci) * L + l];
            s_in[ci][x] = v;
        }
        for (int idx = tid; idx < CIC * K * COT; idx += 256) {
            int co = idx % COT;
            int k  = (idx / COT) % K;
            int ci = idx / (COT * K);
            s_w[ci][k][co] = wt[((size_t)(co0 + co) * CI + ci0 + ci) * K + k];
        }
        __syncthreads();
#pragma unroll 4
        for (int ci = 0; ci < CIC; ci++) {
            float x[8 + K - 1];
#pragma unroll
            for (int t = 0; t < 8 + K - 1; t++) x[t] = s_in[ci][ls + t];
#pragma unroll
            for (int k = 0; k < K; k++) {
                float4 w4 = *reinterpret_cast<const float4*>(&s_w[ci][k][cs]);
                float wv[4] = {w4.x, w4.y, w4.z, w4.w};
#pragma unroll
                for (int i = 0; i < 4; i++)
#pragma unroll
                    for (int j = 0; j < 8; j++)
                        acc[i][j] = fmaf(wv[i], x[j + k], acc[i][j]);
            }
        }
        __syncthreads();
    }
#pragma unroll
    for (int i = 0; i < 4; i++) {
        const int co = co0 + cs + i;
        const float bv = bias[co];
        const size_t o = ((size_t)b * CO + co) * L + l0 + ls;
        float v[8];
#pragma unroll
        for (int j = 0; j < 8; j++) v[j] = __fadd_rn(acc[i][j], bv);
        if (ADDRES) {
            float4 r0 = *reinterpret_cast<const float4*>(&res[o]);
            float4 r1 = *reinterpret_cast<const float4*>(&res[o + 4]);
            v[0] = __fadd_rn(v[0], r0.x); v[1] = __fadd_rn(v[1], r0.y);
            v[2] = __fadd_rn(v[2], r0.z); v[3] = __fadd_rn(v[3], r0.w);
            v[4] = __fadd_rn(v[4], r1.x); v[5] = __fadd_rn(v[5], r1.y);
            v[6] = __fadd_rn(v[6], r1.z); v[7] = __fadd_rn(v[7], r1.w);
        }
        if (RELU) {
#pragma unroll
            for (int j = 0; j < 8; j++) v[j] = fmaxf(v[j], 0.f);
        }
        float4 o0 = {v[0], v[1], v[2], v[3]};
        float4 o1 = {v[4], v[5], v[6], v[7]};
        *reinterpret_cast<float4*>(&out[o])     = o0;
        *reinterpret_cast<float4*>(&out[o + 4]) = o1;
    }
}

// =================================================================
// VQ: single-pass fp32 screen with candidate buffer + exact fp64
// refine (refine path bit-identical to R7/R8).
// =================================================================
__global__ void __launch_bounds__(256) k_vq(
    const float* __restrict__ cb, float* __restrict__ resid,
    float* __restrict__ zq, float* __restrict__ counts,
    float* __restrict__ bsums)
{
    extern __shared__ float sm[];
    float* s_code = sm;               // 512*64 codes (fp32)
    float* s_cn   = sm + NEMB * LAT;  // fl32(exact norm)
    const int tid = threadIdx.x;

    for (int idx = tid; idx < NEMB * LAT / 4; idx += 256)
        reinterpret_cast<float4*>(s_code)[idx] =
            reinterpret_cast<const float4*>(cb)[idx];
    __syncthreads();
    for (int e = tid; e < NEMB; e += 256) {
        const float* c = s_code + e * LAT;
        double s = 0.0;
#pragma unroll
        for (int j = 0; j < 64; j++) s = fma((double)c[j], (double)c[j], s);
        s_cn[e] = (float)s;
    }
    __syncthreads();

    const size_t m = (size_t)blockIdx.x * 256 + tid;
    float r[64];
    {
        const float4* g = reinterpret_cast<const float4*>(resid + m * 64);
        float4* rr = reinterpret_cast<float4*>(r);
#pragma unroll
        for (int t = 0; t < 16; t++) rr[t] = g[t];
    }
    double rn64 = 0.0;
#pragma unroll
    for (int j = 0; j < 64; j++) rn64 = fma((double)r[j], (double)r[j], rn64);
    const float rn = (float)rn64;

    float sabs = 0.f;
#pragma unroll
    for (int j = 0; j < 64; j++) sabs = __fadd_rn(sabs, fabsf(r[j]));

    // margin (precomputable): 2*grid quantum + 4*fp32 dot error bound
    const float margin = 4.8e-7f * rn + 6.4e-8f * sabs + 1e-8f;

    // ---- single pass: fp32 keys, running best + candidate superset ----
    float best_ka = 3.4e38f;
    int   cand[16];
    int   nc = 0;
    bool  overflow = false;
    for (int e = 0; e < NEMB; e += 4) {
        const float4* c0 = reinterpret_cast<const float4*>(s_code + (e + 0) * LAT);
        const float4* c1 = reinterpret_cast<const float4*>(s_code + (e + 1) * LAT);
        const float4* c2 = reinterpret_cast<const float4*>(s_code + (e + 2) * LAT);
        const float4* c3 = reinterpret_cast<const float4*>(s_code + (e + 3) * LAT);
        float d0 = 0.f, d1 = 0.f, d2 = 0.f, d3 = 0.f;
#pragma unroll
        for (int t = 0; t < 16; t++) {
            float4 a0 = c0[t], a1 = c1[t], a2 = c2[t], a3 = c3[t];
            float x0 = r[t*4+0], x1 = r[t*4+1], x2 = r[t*4+2], x3 = r[t*4+3];
            d0 = fmaf(a0.x, x0, d0); d0 = fmaf(a0.y, x1, d0);
            d0 = fmaf(a0.z, x2, d0); d0 = fmaf(a0.w, x3, d0);
            d1 = fmaf(a1.x, x0, d1); d1 = fmaf(a1.y, x1, d1);
            d1 = fmaf(a1.z, x2, d1); d1 = fmaf(a1.w, x3, d1);
            d2 = fmaf(a2.x, x0, d2); d2 = fmaf(a2.y, x1, d2);
            d2 = fmaf(a2.z, x2, d2); d2 = fmaf(a2.w, x3, d2);
            d3 = fmaf(a3.x, x0, d3); d3 = fmaf(a3.y, x1, d3);
            d3 = fmaf(a3.z, x2, d3); d3 = fmaf(a3.w, x3, d3);
        }
        float ka[4];
        ka[0] = __fsub_rn(__fadd_rn(rn, s_cn[e + 0]), __fmul_rn(2.f, d0));
        ka[1] = __fsub_rn(__fadd_rn(rn, s_cn[e + 1]), __fmul_rn(2.f, d1));
        ka[2] = __fsub_rn(__fadd_rn(rn, s_cn[e + 2]), __fmul_rn(2.f, d2));
        ka[3] = __fsub_rn(__fadd_rn(rn, s_cn[e + 3]), __fmul_rn(2.f, d3));
#pragma unroll
        for (int i = 0; i < 4; i++) {
            if (ka[i] < best_ka) best_ka = ka[i];
            if (ka[i] <= best_ka + margin) {
                if (nc < 16) cand[nc++] = e + i;
                else overflow = true;
            }
        }
    }
    const float thr = best_ka + margin;

    // ---- exact fp64 refine (bit-identical order) ----
    float best = 3.4e38f;
    int bi = 0;
    if (!overflow) {
        for (int ci = 0; ci < nc; ci++) {
            int e = cand[ci];
            // re-check against final threshold (superset pruning)
            const float* c = s_code + (size_t)e * LAT;
            double dd = 0.0;
#pragma unroll
            for (int j = 0; j < 64; j++)
                dd = fma((double)c[j], (double)r[j], dd);
            float dot = (float)dd;
            float dist = __fsub_rn(__fadd_rn(rn, s_cn[e]),
                                   __fmul_rn(2.f, dot));
            if (dist < best) { best = dist; bi = e; }
        }
    } else {
        for (int e = 0; e < NEMB; e++) {
            const float* c = s_code + (size_t)e * LAT;
            double dd = 0.0;
#pragma unroll
            for (int j = 0; j < 64; j++)
                dd = fma((double)c[j], (double)r[j], dd);
            float dot = (float)dd;
            float dist = __fsub_rn(__fadd_rn(rn, s_cn[e]),
                                   __fmul_rn(2.f, dot));
            if (dist < best) { best = dist; bi = e; }
        }
    }
    (void)thr;

    // straight-through update (exact fp32, unchanged bit-path)
    float sq = 0.f;
    {
        const float* c = s_code + bi * LAT;
        float4* rg = reinterpret_cast<float4*>(resid + m * 64);
        float4* zg = reinterpret_cast<float4*>(zq + m * 64);
#pragma unroll
        for (int t = 0; t < 16; t++) {
            float4 zv = zg[t];
            float q[4] = {c[t*4+0], c[t*4+1], c[t*4+2], c[t*4+3]};
            float rv[4] = {r[t*4+0], r[t*4+1], r[t*4+2], r[t*4+3]};
            float4 nr, nz;
            float o_r[4], o_z[4];
#pragma unroll
            for (int u = 0; u < 4; u++) {
                float d  = __fsub_rn(q[u], rv[u]);
                sq = __fadd_rn(sq, __fmul_rn(d, d));
                float qs = __fadd_rn(rv[u], d);
                o_r[u] = __fsub_rn(rv[u], qs);
                o_z[u] = __fadd_rn((&zv.x)[u], qs);
            }
            nr.x = o_r[0]; nr.y = o_r[1]; nr.z = o_r[2]; nr.w = o_r[3];
            nz.x = o_z[0]; nz.y = o_z[1]; nz.z = o_z[2]; nz.w = o_z[3];
            rg[t] = nr; zg[t] = nz;
        }
    }
    atomicAdd(&counts[bi], 1.f);

    __shared__ float red[256];
    red[tid] = sq;
    __syncthreads();
    for (int s = 128; s > 0; s >>= 1) {
        if (tid < s) red[tid] += red[tid + s];
        __syncthreads();
    }
    if (tid == 0) bsums[blockIdx.x] = red[0];
}

__global__ void k_perp(const float* __restrict__ bsums, float* __restrict__ counts,
                       float* __restrict__ scal)
{
    __shared__ float red[512];
    __shared__ float red2[512];
    const int t = threadIdx.x;
    float c = counts[t];
    float avg = c * (1.0f / (float)MROWS);
    red[t] = avg * logf(avg + 1e-10f);
    float s2 = 0.f;
    for (int i = t; i < VQBLOCKS; i += 512) s2 += bsums[i];
    red2[t] = s2;
    __syncthreads();
    for (int s = 256; s > 0; s >>= 1) {
        if (t < s) { red[t] += red[t + s]; red2[t] += red2[t + s]; }
        __syncthreads();
    }
    if (t == 0) {
        scal[1] += expf(-red[0]);
        scal[0] += red2[0];
    }
    counts[t] = 0.f;
}

// =================================================================
// decoder ConvTranspose1d(64->256, K=4, s2, p1) + relu (fp32 scalar)
// =================================================================
__global__ void __launch_bounds__(256) k_dect(
    const float* __restrict__ in, const float* __restrict__ wt,
    const float* __restrict__ bias, float* __restrict__ out)
{
    constexpr int OT = 128, COT = 64, CIC = 32;
    __shared__ float s_in[CIC][66];
    __shared__ float s_w[CIC][4][COT];
    const int b   = blockIdx.z;
    const int co0 = blockIdx.y * COT;
    const int o0  = blockIdx.x * OT;
    const int tid = threadIdx.x;
    const int lq = tid & 15, cq = tid >> 4;
    const int os = lq * 8, cs = cq * 4;
    const int lbase = o0 / 2 - 1;

    float acc[4][8];
#pragma unroll
    for (int i = 0; i < 4; i++)
#pragma unroll
        for (int j = 0; j < 8; j++) acc[i][j] = 0.f;

    for (int ci0 = 0; ci0 < LAT; ci0 += CIC) {
        for (int idx = tid; idx < CIC * 66; idx += 256) {
            int ci = idx / 66, x = idx % 66;
            int l = lbase + x;
            float v = 0.f;
            if (l >= 0 && l < LEN1) v = in[((size_t)b * LAT + ci0 + ci) * LEN1 + l];
            s_in[ci][x] = v;
        }
        for (int idx = tid; idx < CIC * 4 * COT; idx += 256) {
            int co = idx & 63;
            int k  = (idx >> 6) & 3;
            int ci = idx >> 8;
            s_w[ci][k][co] = wt[((size_t)(ci0 + ci) * HID + co0 + co) * 4 + k];
        }
        __syncthreads();
#pragma unroll 4
        for (int ci = 0; ci < CIC; ci++) {
            float x[6];
#pragma unroll
            for (int t = 0; t < 6; t++) x[t] = s_in[ci][(os >> 1) + t];
            float4 W0 = *reinterpret_cast<const float4*>(&s_w[ci][0][cs]);
            float4 W1 = *reinterpret_cast<const float4*>(&s_w[ci][1][cs]);
            float4 W2 = *reinterpret_cast<const float4*>(&s_w[ci][2][cs]);
            float4 W3 = *reinterpret_cast<const float4*>(&s_w[ci][3][cs]);
            float wa[4][4] = {{W0.x, W0.y, W0.z, W0.w},
                              {W1.x, W1.y, W1.z, W1.w},
                              {W2.x, W2.y, W2.z, W2.w},
                              {W3.x, W3.y, W3.z, W3.w}};
#pragma unroll
            for (int jj = 0; jj < 4; jj++) {
                float xe0 = x[jj], xe1 = x[jj + 1], xo2 = x[jj + 2];
#pragma unroll
                for (int i = 0; i < 4; i++) {
                    acc[i][2 * jj]     = fmaf(wa[1][i], xe1, fmaf(wa[3][i], xe0, acc[i][2 * jj]));
                    acc[i][2 * jj + 1] = fmaf(wa[0][i], xo2, fmaf(wa[2][i], xe1, acc[i][2 * jj + 1]));
                }
            }
        }
        __syncthreads();
    }
#pragma unroll
    for (int i = 0; i < 4; i++) {
        const int co = co0 + cs + i;
        const float bv = bias[co];
        const size_t o = ((size_t)b * HID + co) * LEN2 + o0 + os;
        float v[8];
#pragma unroll
        for (int j = 0; j < 8; j++) v[j] = fmaxf(__fadd_rn(acc[i][j], bv), 0.f);
        float4 q0 = {v[0], v[1], v[2], v[3]};
        float4 q1 = {v[4], v[5], v[6], v[7]};
        *reinterpret_cast<float4*>(&out[o])     = q0;
        *reinterpret_cast<float4*>(&out[o + 4]) = q1;
    }
}

// =================================================================
// decoder ConvTranspose1d(256->1, K=3, s1, p1) (fp32)
// =================================================================
__global__ void __launch_bounds__(256) k_decfinal(
    const float* __restrict__ in, const float* __restrict__ wt,
    const float* __restrict__ bias, float* __restrict__ out)
{
    __shared__ float s_w[HID * 3];
    __shared__ float s_in[32][258];
    const int b  = blockIdx.y;
    const int o0 = blockIdx.x * 256;
    const int tx = threadIdx.x;
    for (int i = tx; i < HID * 3; i += 256) s_w[i] = wt[i];
    float acc = 0.f;
    for (int cc = 0; cc < HID; cc += 32) {
        __syncthreads();
        for (int idx = tx; idx < 32 * 258; idx += 256) {
            int ci = idx / 258, x = idx % 258;
            int l = o0 - 1 + x;
            s_in[ci][x] = (l >= 0 && l < LEN2)
                        ? in[((size_t)b * HID + cc + ci) * LEN2 + l] : 0.f;
        }
        __syncthreads();
#pragma unroll 8
        for (int ci = 0; ci < 32; ci++) {
            acc = fmaf(s_w[(cc + ci) * 3 + 0], s_in[ci][tx + 2], acc);
            acc = fmaf(s_w[(cc + ci) * 3 + 1], s_in[ci][tx + 1], acc);
            acc = fmaf(s_w[(cc + ci) * 3 + 2], s_in[ci][tx + 0], acc);
        }
    }
    out[(size_t)b * LEN2 + o0 + tx] = __fadd_rn(acc, bias[0]);
}

// =================================================================
// out projection (fp32 scalar)
// =================================================================
__global__ void __launch_bounds__(256) k_outproj(
    const float* __restrict__ dv, const float* __restrict__ W,
    const float* __restrict__ bias, float* __restrict__ out)
{
    constexpr int KC = 32;
    __shared__ float s_d[KC][136];
    __shared__ float s_w[KC][68];
    const int j0  = blockIdx.x * 64;
    const int tid = threadIdx.x;
    const int bq = tid & 15, jq = tid >> 4;
    const int bs = bq * 8, js = jq * 4;
    float acc[8][4];
#pragma unroll
    for (int i = 0; i < 8; i++)
#pragma unroll
        for (int j = 0; j < 4; j++) acc[i][j] = 0.f;

    for (int k0 = 0; k0 < NITEMS; k0 += KC) {
        for (int idx = tid; idx < KC * 128; idx += 256) {
            int bb = idx >> 5, k = idx & 31;
            s_d[k][bb] = dv[(size_t)bb * NITEMS + k0 + k];
        }
        for (int idx = tid; idx < KC * 64; idx += 256) {
            int j = idx >> 5, k = idx & 31;
            s_w[k][j] = W[(size_t)(j0 + j) * NITEMS + k0 + k];
        }
        __syncthreads();
#pragma unroll
        for (int k = 0; k < KC; k++) {
            float4 w4 = *reinterpret_cast<const float4*>(&s_w[k][js]);
            float xb[8];
            *reinterpret_cast<float4*>(&xb[0]) = *reinterpret_cast<const float4*>(&s_d[k][bs]);
            *reinterpret_cast<float4*>(&xb[4]) = *reinterpret_cast<const float4*>(&s_d[k][bs + 4]);
            float wv[4] = {w4.x, w4.y, w4.z, w4.w};
#pragma unroll
            for (int i = 0; i < 8; i++)
#pragma unroll
                for (int j = 0; j < 4; j++)
                    acc[i][j] = fmaf(xb[i], wv[j], acc[i][j]);
        }
        __syncthreads();
    }
#pragma unroll
    for (int i = 0; i < 8; i++) {
#pragma unroll
        for (int j = 0; j < 4; j++)
            out[(size_t)(bs + i) * NITEMS + j0 + js + j] =
                __fadd_rn(acc[i][j], bias[j0 + js + j]);
    }
}

__global__ void k_final(const float* __restrict__ scal, float* __restrict__ out, int out_size)
{
    if (out_size >= BATCH * NITEMS + 2) {
        out[BATCH * NITEMS + 0] = 1.25f * scal[0] * (1.0f / 33554432.0f);
        out[BATCH * NITEMS + 1] = scal[1] * 0.25f;
    }
}

// =================================================================
extern "C" void kernel_launch(void* const* d_in, const int* in_sizes, int n_in,
                              void* d_out, int out_size)
{
    const int*   uid  = (const int*)  d_in[0];
    const float* mat  = (const float*)d_in[1];
    const float* ecw  = (const float*)d_in[2];
    const float* ecb  = (const float*)d_in[3];
    const float* erw1 = (const float*)d_in[4];
    const float* erb1 = (const float*)d_in[5];
    const float* erw2 = (const float*)d_in[6];
    const float* erb2 = (const float*)d_in[7];
    const float* efw  = (const float*)d_in[8];
    const float* efb  = (const float*)d_in[9];
    const float* cbs  = (const float*)d_in[10];
    const float* dtw  = (const float*)d_in[11];
    const float* dtb  = (const float*)d_in[12];
    const float* drw1 = (const float*)d_in[13];
    const float* drb1 = (const float*)d_in[14];
    const float* drw2 = (const float*)d_in[15];
    const float* drb2 = (const float*)d_in[16];
    const float* dfw  = (const float*)d_in[17];
    const float* dfb  = (const float*)d_in[18];
    const float* opw  = (const float*)d_in[19];
    const float* opb  = (const float*)d_in[20];
    float* out = (float*)d_out;

    float *bufA, *bufB, *resid, *zq, *dvec, *counts, *scal, *bsums;
    cudaGetSymbolAddress((void**)&bufA,   g_bufA);
    cudaGetSymbolAddress((void**)&bufB,   g_bufB);
    cudaGetSymbolAddress((void**)&resid,  g_res);
    cudaGetSymbolAddress((void**)&zq,     g_zq);
    cudaGetSymbolAddress((void**)&dvec,   g_dvec);
    cudaGetSymbolAddress((void**)&counts, g_counts);
    cudaGetSymbolAddress((void**)&scal,   g_scal);
    cudaGetSymbolAddress((void**)&bsums,  g_bsums);

    const int vq_smem = (NEMB * LAT + NEMB) * (int)sizeof(float);
    cudaFuncSetAttribute(k_vq, cudaFuncAttributeMaxDynamicSharedMemorySize, vq_smem);

    cudaMemsetAsync(zq, 0, (size_t)33554432 * sizeof(float), 0);
    cudaMemsetAsync(scal, 0, 2 * sizeof(float), 0);
    cudaMemsetAsync(counts, 0, NEMB * sizeof(float), 0);

    // ---------------- encoder (double-float exact, retiled) -------------
    k_enc_conv1<<<dim3(LEN1 / 128, BATCH), 128>>>(uid, mat, ecw, ecb, bufA);
    for (int i = 0; i < 2; i++) {
        k_convdf<3, true, false><<<dim3(LEN1 / 64, HID / 128, BATCH), 256>>>(
            bufA, erw1 + (size_t)i * HID * HID * 3, erb1 + i * HID, nullptr, bufB,
            HID, HID, LEN1);
        k_convdf<1, true, true><<<dim3(LEN1 / 64, HID / 128, BATCH), 256>>>(
            bufB, erw2 + (size_t)i * HID * HID, erb2 + i * HID, bufA, bufA,
            HID, HID, LEN1);
    }
    k_convdf_narrow<3><<<dim3(LEN1 / 64, 1, BATCH), 256>>>(
        bufA, efw, efb, resid, LAT, HID, LEN1);

    // ---------------- residual VQ (single-pass screen + exact refine) ---
    for (int q = 0; q < NQ; q++) {
        k_vq<<<VQBLOCKS, 256, vq_smem>>>(cbs + (size_t)q * NEMB * LAT,
                                         resid, zq, counts, bsums);
        k_perp<<<1, 512>>>(bsums, counts, scal);
    }

    // ---------------- decoder (fp32 scalar) ----------------
    k_dect<<<dim3(LEN2 / 128, HID / 64, BATCH), 256>>>(zq, dtw, dtb, bufA);
    for (int i = 0; i < 2; i++) {
        k_conv<3, true, false><<<dim3(LEN2 / 128, HID / 64, BATCH), 256>>>(
            bufA, drw1 + (size_t)i * HID * HID * 3, drb1 + i * HID, nullptr, bufB,
            HID, HID, LEN2);
        k_conv<1, true, true><<<dim3(LEN2 / 128, HID / 64, BATCH), 256>>>(
            bufB, drw2 + (size_t)i * HID * HID, drb2 + i * HID, bufA, bufA,
            HID, HID, LEN2);
    }
    k_decfinal<<<dim3(LEN2 / 256, BATCH), 256>>>(bufA, dfw, dfb, dvec);

    // ---------------- output projection + scalars ----------------
    k_outproj<<<NITEMS / 64, 256>>>(dvec, opw, opb, out);
    k_final<<<1, 1>>>(scal, out, out_size);
}

// round 11
// speedup vs baseline: 1.3666x; 1.3418x over previous
#include <cuda_runtime.h>
#include <math.h>

#define BATCH   128
#define NITEMS  8192
#define HID     256
#define LAT     64
#define LEN1    4096
#define LEN2    8192
#define NEMB    512
#define NQ      4
#define MROWS   524288
#define VQBLOCKS 2048

// ---------------- scratch ----------------
__device__ float g_bufA[268435456];
__device__ float g_bufB[268435456];
__device__ float g_res [33554432];
__device__ float g_zq  [33554432];
__device__ float g_dvec[BATCH * NITEMS];
__device__ float g_counts[NEMB];
__device__ float g_scal[2];
__device__ float g_bsums[VQBLOCKS];
__device__ unsigned int g_xmax[8];
__device__ float g_Cval[8][256];

// =================================================================
// abs-max reduction (inputs are post-relu, >= 0 -> uint ordering ok)
// =================================================================
__global__ void __launch_bounds__(256) k_absmax(
    const float* __restrict__ x, size_t n4, int slot)
{
    __shared__ float red[256];
    const float4* x4 = reinterpret_cast<const float4*>(x);
    float m = 0.f;
    for (size_t i = (size_t)blockIdx.x * 256 + threadIdx.x; i < n4;
         i += (size_t)gridDim.x * 256) {
        float4 v = x4[i];
        m = fmaxf(m, fmaxf(fmaxf(v.x, v.y), fmaxf(v.z, v.w)));
    }
    red[threadIdx.x] = m;
    __syncthreads();
    for (int s = 128; s > 0; s >>= 1) {
        if (threadIdx.x < s) red[threadIdx.x] = fmaxf(red[threadIdx.x], red[threadIdx.x + s]);
        __syncthreads();
    }
    if (threadIdx.x == 0)
        atomicMax(&g_xmax[slot], __float_as_uint(red[0]));
}

// per-output-channel grid constant: C = 2^(ilogb(L1(w)*xmax)+3)
__global__ void k_makeC(const float* __restrict__ wt, int CO, int CIK, int slot)
{
    int co = threadIdx.x;
    if (co >= CO) return;
    float l1 = 0.f;
    const float* w = wt + (size_t)co * CIK;
    for (int i = 0; i < CIK; i++) l1 += fabsf(w[i]);
    float xm = __uint_as_float(g_xmax[slot]);
    float B = l1 * xm;
    float C = 1.0f;
    if (B > 0.f) C = ldexpf(1.0f, ilogbf(B) + 3);
    g_Cval[slot][co] = C;
}

// =================================================================
// encoder conv1 (fp64-exact, tiny)
// =================================================================
__global__ void __launch_bounds__(128) k_enc_conv1(
    const int* __restrict__ uid, const float* __restrict__ mat,
    const float* __restrict__ w, const float* __restrict__ bias,
    float* __restrict__ out)
{
    __shared__ float s_in[258];
    __shared__ float s_w[HID * 4];
    const int b  = blockIdx.y;
    const int l0 = blockIdx.x * 128;
    const int tx = threadIdx.x;
    const float* row = mat + (size_t)uid[b] * NITEMS;
    for (int i = tx; i < 258; i += 128) {
        int g = 2 * l0 - 1 + i;
        s_in[i] = (g >= 0 && g < NITEMS) ? row[g] : 0.f;
    }
    for (int i = tx; i < HID * 4; i += 128) s_w[i] = w[i];
    __syncthreads();
    const double x0 = s_in[2 * tx + 0], x1 = s_in[2 * tx + 1];
    const double x2 = s_in[2 * tx + 2], x3 = s_in[2 * tx + 3];
    const int l = l0 + tx;
    for (int co = 0; co < HID; co++) {
        double a = 0.0;
        a = fma((double)s_w[co * 4 + 0], x0, a);
        a = fma((double)s_w[co * 4 + 1], x1, a);
        a = fma((double)s_w[co * 4 + 2], x2, a);
        a = fma((double)s_w[co * 4 + 3], x3, a);
        float v = __fadd_rn((float)a, bias[co]);
        out[((size_t)b * HID + co) * LEN1 + l] = fmaxf(v, 0.f);
    }
}

// =================================================================
// encoder conv1d, grid-accumulator exact (4 ops/MAC):
//   A init = C (on 2^k grid, C >= 2*sum|w*x|)
//   t = fma(w,x,A); d = t-A (exact); e = fma(w,x,-d); E += e; A = t
//   S = fl( fl((A-C)+E) )   — deviation from exact conv ~2^-36*S_max
// Tile 64co x 64l, 256 thr, per-thread 4co x 4l (R8 tile, regs ~64)
// =================================================================
template <int K, bool RELU, bool ADDRES>
__global__ void __launch_bounds__(256) k_convgrid(
    const float* __restrict__ in, const float* __restrict__ wt,
    const float* __restrict__ bias, const float* __restrict__ res,
    float* __restrict__ out, int CO, int CI, int L, int slot)
{
    constexpr int PAD = (K - 1) / 2;
    constexpr int LT = 64, COT = 64, CIC = 16;
    constexpr int LW = LT + 2 * PAD;
    __shared__ float s_in[CIC][LW];
    __shared__ float s_w[CIC][K][COT];

    const int b   = blockIdx.z;
    const int co0 = blockIdx.y * COT;
    const int l0  = blockIdx.x * LT;
    const int tid = threadIdx.x;
    const int lq = tid & 15, cq = tid >> 4;
    const int ls = lq * 4, cs = cq * 4;

    float Cc[4];
#pragma unroll
    for (int i = 0; i < 4; i++) Cc[i] = g_Cval[slot][co0 + cs + i];

    float A[4][4], E[4][4];
#pragma unroll
    for (int i = 0; i < 4; i++)
#pragma unroll
        for (int j = 0; j < 4; j++) { A[i][j] = Cc[i]; E[i][j] = 0.f; }

    for (int ci0 = 0; ci0 < CI; ci0 += CIC) {
        for (int idx = tid; idx < CIC * LW; idx += 256) {
            int ci = idx / LW, x = idx % LW;
            int l = l0 - PAD + x;
            float v = 0.f;
            if (l >= 0 && l < L) v = in[((size_t)b * CI + ci0 + ci) * L + l];
            s_in[ci][x] = v;
        }
        for (int idx = tid; idx < CIC * K * COT; idx += 256) {
            int co = idx % COT;
            int k  = (idx / COT) % K;
            int ci = idx / (COT * K);
            s_w[ci][k][co] = wt[((size_t)(co0 + co) * CI + ci0 + ci) * K + k];
        }
        __syncthreads();
#pragma unroll 2
        for (int ci = 0; ci < CIC; ci++) {
            float x[4 + K - 1];
#pragma unroll
            for (int t = 0; t < 4 + K - 1; t++) x[t] = s_in[ci][ls + t];
#pragma unroll
            for (int k = 0; k < K; k++) {
                float4 w4 = *reinterpret_cast<const float4*>(&s_w[ci][k][cs]);
                float wv[4] = {w4.x, w4.y, w4.z, w4.w};
#pragma unroll
                for (int i = 0; i < 4; i++)
#pragma unroll
                    for (int j = 0; j < 4; j++) {
                        float t2 = __fmaf_rn(wv[i], x[j + k], A[i][j]);
                        float d  = __fsub_rn(t2, A[i][j]);
                        float e  = __fmaf_rn(wv[i], x[j + k], -d);
                        E[i][j]  = __fadd_rn(E[i][j], e);
                        A[i][j]  = t2;
                    }
            }
        }
        __syncthreads();
    }
#pragma unroll
    for (int i = 0; i < 4; i++) {
        const int co = co0 + cs + i;
        const float bv = bias[co];
        const size_t o = ((size_t)b * CO + co) * L + l0 + ls;
        float v[4];
#pragma unroll
        for (int j = 0; j < 4; j++) {
            float hi = __fsub_rn(A[i][j], Cc[i]);       // exact
            v[j] = __fadd_rn(__fadd_rn(hi, E[i][j]), bv);
        }
        if (ADDRES) {
            float4 r0 = *reinterpret_cast<const float4*>(&res[o]);
            v[0] = __fadd_rn(v[0], r0.x); v[1] = __fadd_rn(v[1], r0.y);
            v[2] = __fadd_rn(v[2], r0.z); v[3] = __fadd_rn(v[3], r0.w);
        }
        if (RELU) {
#pragma unroll
            for (int j = 0; j < 4; j++) v[j] = fmaxf(v[j], 0.f);
        }
        float4 o0 = {v[0], v[1], v[2], v[3]};
        *reinterpret_cast<float4*>(&out[o]) = o0;
    }
}

// =================================================================
// decoder conv1d (fp32 scalar, R8 version), K in {1,3}
// =================================================================
template <int K, bool RELU, bool ADDRES>
__global__ void __launch_bounds__(256) k_conv(
    const float* __restrict__ in, const float* __restrict__ wt,
    const float* __restrict__ bias, const float* __restrict__ res,
    float* __restrict__ out, int CO, int CI, int L)
{
    constexpr int PAD = (K - 1) / 2;
    constexpr int LT = 128, COT = 64, CIC = 16;
    constexpr int LW = LT + 2 * PAD;
    __shared__ float s_in[CIC][LW];
    __shared__ float s_w[CIC][K][COT];

    const int b   = blockIdx.z;
    const int co0 = blockIdx.y * COT;
    const int l0  = blockIdx.x * LT;
    const int tid = threadIdx.x;
    const int lq = tid & 15, cq = tid >> 4;
    const int ls = lq * 8, cs = cq * 4;

    float acc[4][8];
#pragma unroll
    for (int i = 0; i < 4; i++)
#pragma unroll
        for (int j = 0; j < 8; j++) acc[i][j] = 0.f;

    for (int ci0 = 0; ci0 < CI; ci0 += CIC) {
        for (int idx = tid; idx < CIC * LW; idx += 256) {
            int ci = idx / LW, x = idx % LW;
            int l = l0 - PAD + x;
            float v = 0.f;
            if (l >= 0 && l < L) v = in[((size_t)b * CI + ci0 + ci) * L + l];
            s_in[ci][x] = v;
        }
        for (int idx = tid; idx < CIC * K * COT; idx += 256) {
            int co = idx % COT;
            int k  = (idx / COT) % K;
            int ci = idx / (COT * K);
            s_w[ci][k][co] = wt[((size_t)(co0 + co) * CI + ci0 + ci) * K + k];
        }
        __syncthreads();
#pragma unroll 4
        for (int ci = 0; ci < CIC; ci++) {
            float x[8 + K - 1];
#pragma unroll
            for (int t = 0; t < 8 + K - 1; t++) x[t] = s_in[ci][ls + t];
#pragma unroll
            for (int k = 0; k < K; k++) {
                float4 w4 = *reinterpret_cast<const float4*>(&s_w[ci][k][cs]);
                float wv[4] = {w4.x, w4.y, w4.z, w4.w};
#pragma unroll
                for (int i = 0; i < 4; i++)
#pragma unroll
                    for (int j = 0; j < 8; j++)
                        acc[i][j] = fmaf(wv[i], x[j + k], acc[i][j]);
            }
        }
        __syncthreads();
    }
#pragma unroll
    for (int i = 0; i < 4; i++) {
        const int co = co0 + cs + i;
        const float bv = bias[co];
        const size_t o = ((size_t)b * CO + co) * L + l0 + ls;
        float v[8];
#pragma unroll
        for (int j = 0; j < 8; j++) v[j] = __fadd_rn(acc[i][j], bv);
        if (ADDRES) {
            float4 r0 = *reinterpret_cast<const float4*>(&res[o]);
            float4 r1 = *reinterpret_cast<const float4*>(&res[o + 4]);
            v[0] = __fadd_rn(v[0], r0.x); v[1] = __fadd_rn(v[1], r0.y);
            v[2] = __fadd_rn(v[2], r0.z); v[3] = __fadd_rn(v[3], r0.w);
            v[4] = __fadd_rn(v[4], r1.x); v[5] = __fadd_rn(v[5], r1.y);
            v[6] = __fadd_rn(v[6], r1.z); v[7] = __fadd_rn(v[7], r1.w);
        }
        if (RELU) {
#pragma unroll
            for (int j = 0; j < 8; j++) v[j] = fmaxf(v[j], 0.f);
        }
        float4 o0 = {v[0], v[1], v[2], v[3]};
        float4 o1 = {v[4], v[5], v[6], v[7]};
        *reinterpret_cast<float4*>(&out[o])     = o0;
        *reinterpret_cast<float4*>(&out[o + 4]) = o1;
    }
}

// =================================================================
// VQ: single-pass fp32 screen + exact fp64 refine (R10)
// =================================================================
__global__ void __launch_bounds__(256) k_vq(
    const float* __restrict__ cb, float* __restrict__ resid,
    float* __restrict__ zq, float* __restrict__ counts,
    float* __restrict__ bsums)
{
    extern __shared__ float sm[];
    float* s_code = sm;
    float* s_cn   = sm + NEMB * LAT;
    const int tid = threadIdx.x;

    for (int idx = tid; idx < NEMB * LAT / 4; idx += 256)
        reinterpret_cast<float4*>(s_code)[idx] =
            reinterpret_cast<const float4*>(cb)[idx];
    __syncthreads();
    for (int e = tid; e < NEMB; e += 256) {
        const float* c = s_code + e * LAT;
        double s = 0.0;
#pragma unroll
        for (int j = 0; j < 64; j++) s = fma((double)c[j], (double)c[j], s);
        s_cn[e] = (float)s;
    }
    __syncthreads();

    const size_t m = (size_t)blockIdx.x * 256 + tid;
    float r[64];
    {
        const float4* g = reinterpret_cast<const float4*>(resid + m * 64);
        float4* rr = reinterpret_cast<float4*>(r);
#pragma unroll
        for (int t = 0; t < 16; t++) rr[t] = g[t];
    }
    double rn64 = 0.0;
#pragma unroll
    for (int j = 0; j < 64; j++) rn64 = fma((double)r[j], (double)r[j], rn64);
    const float rn = (float)rn64;

    float sabs = 0.f;
#pragma unroll
    for (int j = 0; j < 64; j++) sabs = __fadd_rn(sabs, fabsf(r[j]));

    const float margin = 4.8e-7f * rn + 6.4e-8f * sabs + 1e-8f;

    float best_ka = 3.4e38f;
    int   cand[16];
    int   nc = 0;
    bool  overflow = false;
    for (int e = 0; e < NEMB; e += 4) {
        const float4* c0 = reinterpret_cast<const float4*>(s_code + (e + 0) * LAT);
        const float4* c1 = reinterpret_cast<const float4*>(s_code + (e + 1) * LAT);
        const float4* c2 = reinterpret_cast<const float4*>(s_code + (e + 2) * LAT);
        const float4* c3 = reinterpret_cast<const float4*>(s_code + (e + 3) * LAT);
        float d0 = 0.f, d1 = 0.f, d2 = 0.f, d3 = 0.f;
#pragma unroll
        for (int t = 0; t < 16; t++) {
            float4 a0 = c0[t], a1 = c1[t], a2 = c2[t], a3 = c3[t];
            float x0 = r[t*4+0], x1 = r[t*4+1], x2 = r[t*4+2], x3 = r[t*4+3];
            d0 = fmaf(a0.x, x0, d0); d0 = fmaf(a0.y, x1, d0);
            d0 = fmaf(a0.z, x2, d0); d0 = fmaf(a0.w, x3, d0);
            d1 = fmaf(a1.x, x0, d1); d1 = fmaf(a1.y, x1, d1);
            d1 = fmaf(a1.z, x2, d1); d1 = fmaf(a1.w, x3, d1);
            d2 = fmaf(a2.x, x0, d2); d2 = fmaf(a2.y, x1, d2);
            d2 = fmaf(a2.z, x2, d2); d2 = fmaf(a2.w, x3, d2);
            d3 = fmaf(a3.x, x0, d3); d3 = fmaf(a3.y, x1, d3);
            d3 = fmaf(a3.z, x2, d3); d3 = fmaf(a3.w, x3, d3);
        }
        float ka[4];
        ka[0] = __fsub_rn(__fadd_rn(rn, s_cn[e + 0]), __fmul_rn(2.f, d0));
        ka[1] = __fsub_rn(__fadd_rn(rn, s_cn[e + 1]), __fmul_rn(2.f, d1));
        ka[2] = __fsub_rn(__fadd_rn(rn, s_cn[e + 2]), __fmul_rn(2.f, d2));
        ka[3] = __fsub_rn(__fadd_rn(rn, s_cn[e + 3]), __fmul_rn(2.f, d3));
#pragma unroll
        for (int i = 0; i < 4; i++) {
            if (ka[i] < best_ka) best_ka = ka[i];
            if (ka[i] <= best_ka + margin) {
                if (nc < 16) cand[nc++] = e + i;
                else overflow = true;
            }
        }
    }

    float best = 3.4e38f;
    int bi = 0;
    if (!overflow) {
        for (int ci = 0; ci < nc; ci++) {
            int e = cand[ci];
            const float* c = s_code + (size_t)e * LAT;
            double dd = 0.0;
#pragma unroll
            for (int j = 0; j < 64; j++)
                dd = fma((double)c[j], (double)r[j], dd);
            float dot = (float)dd;
            float dist = __fsub_rn(__fadd_rn(rn, s_cn[e]),
                                   __fmul_rn(2.f, dot));
            if (dist < best) { best = dist; bi = e; }
        }
    } else {
        for (int e = 0; e < NEMB; e++) {
            const float* c = s_code + (size_t)e * LAT;
            double dd = 0.0;
#pragma unroll
            for (int j = 0; j < 64; j++)
                dd = fma((double)c[j], (double)r[j], dd);
            float dot = (float)dd;
            float dist = __fsub_rn(__fadd_rn(rn, s_cn[e]),
                                   __fmul_rn(2.f, dot));
            if (dist < best) { best = dist; bi = e; }
        }
    }

    float sq = 0.f;
    {
        const float* c = s_code + bi * LAT;
        float4* rg = reinterpret_cast<float4*>(resid + m * 64);
        float4* zg = reinterpret_cast<float4*>(zq + m * 64);
#pragma unroll
        for (int t = 0; t < 16; t++) {
            float4 zv = zg[t];
            float q[4] = {c[t*4+0], c[t*4+1], c[t*4+2], c[t*4+3]};
            float rv[4] = {r[t*4+0], r[t*4+1], r[t*4+2], r[t*4+3]};
            float4 nr, nz;
            float o_r[4], o_z[4];
#pragma unroll
            for (int u = 0; u < 4; u++) {
                float d  = __fsub_rn(q[u], rv[u]);
                sq = __fadd_rn(sq, __fmul_rn(d, d));
                float qs = __fadd_rn(rv[u], d);
                o_r[u] = __fsub_rn(rv[u], qs);
                o_z[u] = __fadd_rn((&zv.x)[u], qs);
            }
            nr.x = o_r[0]; nr.y = o_r[1]; nr.z = o_r[2]; nr.w = o_r[3];
            nz.x = o_z[0]; nz.y = o_z[1]; nz.z = o_z[2]; nz.w = o_z[3];
            rg[t] = nr; zg[t] = nz;
        }
    }
    atomicAdd(&counts[bi], 1.f);

    __shared__ float red[256];
    red[tid] = sq;
    __syncthreads();
    for (int s = 128; s > 0; s >>= 1) {
        if (tid < s) red[tid] += red[tid + s];
        __syncthreads();
    }
    if (tid == 0) bsums[blockIdx.x] = red[0];
}

__global__ void k_perp(const float* __restrict__ bsums, float* __restrict__ counts,
                       float* __restrict__ scal)
{
    __shared__ float red[512];
    __shared__ float red2[512];
    const int t = threadIdx.x;
    float c = counts[t];
    float avg = c * (1.0f / (float)MROWS);
    red[t] = avg * logf(avg + 1e-10f);
    float s2 = 0.f;
    for (int i = t; i < VQBLOCKS; i += 512) s2 += bsums[i];
    red2[t] = s2;
    __syncthreads();
    for (int s = 256; s > 0; s >>= 1) {
        if (t < s) { red[t] += red[t + s]; red2[t] += red2[t + s]; }
        __syncthreads();
    }
    if (t == 0) {
        scal[1] += expf(-red[0]);
        scal[0] += red2[0];
    }
    counts[t] = 0.f;
}

// =================================================================
// decoder ConvTranspose1d(64->256, K=4, s2, p1) + relu (fp32 scalar)
// =================================================================
__global__ void __launch_bounds__(256) k_dect(
    const float* __restrict__ in, const float* __restrict__ wt,
    const float* __restrict__ bias, float* __restrict__ out)
{
    constexpr int OT = 128, COT = 64, CIC = 32;
    __shared__ float s_in[CIC][66];
    __shared__ float s_w[CIC][4][COT];
    const int b   = blockIdx.z;
    const int co0 = blockIdx.y * COT;
    const int o0  = blockIdx.x * OT;
    const int tid = threadIdx.x;
    const int lq = tid & 15, cq = tid >> 4;
    const int os = lq * 8, cs = cq * 4;
    const int lbase = o0 / 2 - 1;

    float acc[4][8];
#pragma unroll
    for (int i = 0; i < 4; i++)
#pragma unroll
        for (int j = 0; j < 8; j++) acc[i][j] = 0.f;

    for (int ci0 = 0; ci0 < LAT; ci0 += CIC) {
        for (int idx = tid; idx < CIC * 66; idx += 256) {
            int ci = idx / 66, x = idx % 66;
            int l = lbase + x;
            float v = 0.f;
            if (l >= 0 && l < LEN1) v = in[((size_t)b * LAT + ci0 + ci) * LEN1 + l];
            s_in[ci][x] = v;
        }
        for (int idx = tid; idx < CIC * 4 * COT; idx += 256) {
            int co = idx & 63;
            int k  = (idx >> 6) & 3;
            int ci = idx >> 8;
            s_w[ci][k][co] = wt[((size_t)(ci0 + ci) * HID + co0 + co) * 4 + k];
        }
        __syncthreads();
#pragma unroll 4
        for (int ci = 0; ci < CIC; ci++) {
            float x[6];
#pragma unroll
            for (int t = 0; t < 6; t++) x[t] = s_in[ci][(os >> 1) + t];
            float4 W0 = *reinterpret_cast<const float4*>(&s_w[ci][0][cs]);
            float4 W1 = *reinterpret_cast<const float4*>(&s_w[ci][1][cs]);
            float4 W2 = *reinterpret_cast<const float4*>(&s_w[ci][2][cs]);
            float4 W3 = *reinterpret_cast<const float4*>(&s_w[ci][3][cs]);
            float wa[4][4] = {{W0.x, W0.y, W0.z, W0.w},
                              {W1.x, W1.y, W1.z, W1.w},
                              {W2.x, W2.y, W2.z, W2.w},
                              {W3.x, W3.y, W3.z, W3.w}};
#pragma unroll
            for (int jj = 0; jj < 4; jj++) {
                float xe0 = x[jj], xe1 = x[jj + 1], xo2 = x[jj + 2];
#pragma unroll
                for (int i = 0; i < 4; i++) {
                    acc[i][2 * jj]     = fmaf(wa[1][i], xe1, fmaf(wa[3][i], xe0, acc[i][2 * jj]));
                    acc[i][2 * jj + 1] = fmaf(wa[0][i], xo2, fmaf(wa[2][i], xe1, acc[i][2 * jj + 1]));
                }
            }
        }
        __syncthreads();
    }
#pragma unroll
    for (int i = 0; i < 4; i++) {
        const int co = co0 + cs + i;
        const float bv = bias[co];
        const size_t o = ((size_t)b * HID + co) * LEN2 + o0 + os;
        float v[8];
#pragma unroll
        for (int j = 0; j < 8; j++) v[j] = fmaxf(__fadd_rn(acc[i][j], bv), 0.f);
        float4 q0 = {v[0], v[1], v[2], v[3]};
        float4 q1 = {v[4], v[5], v[6], v[7]};
        *reinterpret_cast<float4*>(&out[o])     = q0;
        *reinterpret_cast<float4*>(&out[o + 4]) = q1;
    }
}

// =================================================================
// decoder ConvTranspose1d(256->1, K=3, s1, p1) (fp32)
// =================================================================
__global__ void __launch_bounds__(256) k_decfinal(
    const float* __restrict__ in, const float* __restrict__ wt,
    const float* __restrict__ bias, float* __restrict__ out)
{
    __shared__ float s_w[HID * 3];
    __shared__ float s_in[32][258];
    const int b  = blockIdx.y;
    const int o0 = blockIdx.x * 256;
    const int tx = threadIdx.x;
    for (int i = tx; i < HID * 3; i += 256) s_w[i] = wt[i];
    float acc = 0.f;
    for (int cc = 0; cc < HID; cc += 32) {
        __syncthreads();
        for (int idx = tx; idx < 32 * 258; idx += 256) {
            int ci = idx / 258, x = idx % 258;
            int l = o0 - 1 + x;
            s_in[ci][x] = (l >= 0 && l < LEN2)
                        ? in[((size_t)b * HID + cc + ci) * LEN2 + l] : 0.f;
        }
        __syncthreads();
#pragma unroll 8
        for (int ci = 0; ci < 32; ci++) {
            acc = fmaf(s_w[(cc + ci) * 3 + 0], s_in[ci][tx + 2], acc);
            acc = fmaf(s_w[(cc + ci) * 3 + 1], s_in[ci][tx + 1], acc);
            acc = fmaf(s_w[(cc + ci) * 3 + 2], s_in[ci][tx + 0], acc);
        }
    }
    out[(size_t)b * LEN2 + o0 + tx] = __fadd_rn(acc, bias[0]);
}

// =================================================================
// out projection (fp32 scalar)
// =================================================================
__global__ void __launch_bounds__(256) k_outproj(
    const float* __restrict__ dv, const float* __restrict__ W,
    const float* __restrict__ bias, float* __restrict__ out)
{
    constexpr int KC = 32;
    __shared__ float s_d[KC][136];
    __shared__ float s_w[KC][68];
    const int j0  = blockIdx.x * 64;
    const int tid = threadIdx.x;
    const int bq = tid & 15, jq = tid >> 4;
    const int bs = bq * 8, js = jq * 4;
    float acc[8][4];
#pragma unroll
    for (int i = 0; i < 8; i++)
#pragma unroll
        for (int j = 0; j < 4; j++) acc[i][j] = 0.f;

    for (int k0 = 0; k0 < NITEMS; k0 += KC) {
        for (int idx = tid; idx < KC * 128; idx += 256) {
            int bb = idx >> 5, k = idx & 31;
            s_d[k][bb] = dv[(size_t)bb * NITEMS + k0 + k];
        }
        for (int idx = tid; idx < KC * 64; idx += 256) {
            int j = idx >> 5, k = idx & 31;
            s_w[k][j] = W[(size_t)(j0 + j) * NITEMS + k0 + k];
        }
        __syncthreads();
#pragma unroll
        for (int k = 0; k < KC; k++) {
            float4 w4 = *reinterpret_cast<const float4*>(&s_w[k][js]);
            float xb[8];
            *reinterpret_cast<float4*>(&xb[0]) = *reinterpret_cast<const float4*>(&s_d[k][bs]);
            *reinterpret_cast<float4*>(&xb[4]) = *reinterpret_cast<const float4*>(&s_d[k][bs + 4]);
            float wv[4] = {w4.x, w4.y, w4.z, w4.w};
#pragma unroll
            for (int i = 0; i < 8; i++)
#pragma unroll
                for (int j = 0; j < 4; j++)
                    acc[i][j] = fmaf(xb[i], wv[j], acc[i][j]);
        }
        __syncthreads();
    }
#pragma unroll
    for (int i = 0; i < 8; i++) {
#pragma unroll
        for (int j = 0; j < 4; j++)
            out[(size_t)(bs + i) * NITEMS + j0 + js + j] =
                __fadd_rn(acc[i][j], bias[j0 + js + j]);
    }
}

__global__ void k_final(const float* __restrict__ scal, float* __restrict__ out, int out_size)
{
    if (out_size >= BATCH * NITEMS + 2) {
        out[BATCH * NITEMS + 0] = 1.25f * scal[0] * (1.0f / 33554432.0f);
        out[BATCH * NITEMS + 1] = scal[1] * 0.25f;
    }
}

// =================================================================
extern "C" void kernel_launch(void* const* d_in, const int* in_sizes, int n_in,
                              void* d_out, int out_size)
{
    const int*   uid  = (const int*)  d_in[0];
    const float* mat  = (const float*)d_in[1];
    const float* ecw  = (const float*)d_in[2];
    const float* ecb  = (const float*)d_in[3];
    const float* erw1 = (const float*)d_in[4];
    const float* erb1 = (const float*)d_in[5];
    const float* erw2 = (const float*)d_in[6];
    const float* erb2 = (const float*)d_in[7];
    const float* efw  = (const float*)d_in[8];
    const float* efb  = (const float*)d_in[9];
    const float* cbs  = (const float*)d_in[10];
    const float* dtw  = (const float*)d_in[11];
    const float* dtb  = (const float*)d_in[12];
    const float* drw1 = (const float*)d_in[13];
    const float* drb1 = (const float*)d_in[14];
    const float* drw2 = (const float*)d_in[15];
    const float* drb2 = (const float*)d_in[16];
    const float* dfw  = (const float*)d_in[17];
    const float* dfb  = (const float*)d_in[18];
    const float* opw  = (const float*)d_in[19];
    const float* opb  = (const float*)d_in[20];
    float* out = (float*)d_out;

    float *bufA, *bufB, *resid, *zq, *dvec, *counts, *scal, *bsums;
    unsigned int* xmax;
    cudaGetSymbolAddress((void**)&bufA,   g_bufA);
    cudaGetSymbolAddress((void**)&bufB,   g_bufB);
    cudaGetSymbolAddress((void**)&resid,  g_res);
    cudaGetSymbolAddress((void**)&zq,     g_zq);
    cudaGetSymbolAddress((void**)&dvec,   g_dvec);
    cudaGetSymbolAddress((void**)&counts, g_counts);
    cudaGetSymbolAddress((void**)&scal,   g_scal);
    cudaGetSymbolAddress((void**)&bsums,  g_bsums);
    cudaGetSymbolAddress((void**)&xmax,   g_xmax);

    const int vq_smem = (NEMB * LAT + NEMB) * (int)sizeof(float);
    cudaFuncSetAttribute(k_vq, cudaFuncAttributeMaxDynamicSharedMemorySize, vq_smem);

    cudaMemsetAsync(zq, 0, (size_t)33554432 * sizeof(float), 0);
    cudaMemsetAsync(scal, 0, 2 * sizeof(float), 0);
    cudaMemsetAsync(counts, 0, NEMB * sizeof(float), 0);
    cudaMemsetAsync(xmax, 0, 8 * sizeof(unsigned int), 0);

    const size_t NBIG4 = (size_t)BATCH * HID * LEN1 / 4;   // 33.5M float4

    // ---------------- encoder (grid-accumulator exact) -------------
    k_enc_conv1<<<dim3(LEN1 / 128, BATCH), 128>>>(uid, mat, ecw, ecb, bufA);

    k_absmax<<<1024, 256>>>(bufA, NBIG4, 0);
    k_makeC<<<1, 256>>>(erw1, HID, HID * 3, 0);
    k_convgrid<3, true, false><<<dim3(LEN1 / 64, HID / 64, BATCH), 256>>>(
        bufA, erw1, erb1, nullptr, bufB, HID, HID, LEN1, 0);

    k_absmax<<<1024, 256>>>(bufB, NBIG4, 1);
    k_makeC<<<1, 256>>>(erw2, HID, HID * 1, 1);
    k_convgrid<1, true, true><<<dim3(LEN1 / 64, HID / 64, BATCH), 256>>>(
        bufB, erw2, erb2, bufA, bufA, HID, HID, LEN1, 1);

    k_absmax<<<1024, 256>>>(bufA, NBIG4, 2);
    k_makeC<<<1, 256>>>(erw1 + (size_t)HID * HID * 3, HID, HID * 3, 2);
    k_convgrid<3, true, false><<<dim3(LEN1 / 64, HID / 64, BATCH), 256>>>(
        bufA, erw1 + (size_t)HID * HID * 3, erb1 + HID, nullptr, bufB,
        HID, HID, LEN1, 2);

    k_absmax<<<1024, 256>>>(bufB, NBIG4, 3);
    k_makeC<<<1, 256>>>(erw2 + (size_t)HID * HID, HID, HID * 1, 3);
    k_convgrid<1, true, true><<<dim3(LEN1 / 64, HID / 64, BATCH), 256>>>(
        bufB, erw2 + (size_t)HID * HID, erb2 + HID, bufA, bufA,
        HID, HID, LEN1, 3);

    k_absmax<<<1024, 256>>>(bufA, NBIG4, 4);
    k_makeC<<<1, 256>>>(efw, LAT, HID * 3, 4);
    k_convgrid<3, false, false><<<dim3(LEN1 / 64, LAT / 64, BATCH), 256>>>(
        bufA, efw, efb, nullptr, resid, LAT, HID, LEN1, 4);

    // ---------------- residual VQ (single-pass screen + exact refine) ---
    for (int q = 0; q < NQ; q++) {
        k_vq<<<VQBLOCKS, 256, vq_smem>>>(cbs + (size_t)q * NEMB * LAT,
                                         resid, zq, counts, bsums);
        k_perp<<<1, 512>>>(bsums, counts, scal);
    }

    // ---------------- decoder (fp32 scalar) ----------------
    k_dect<<<dim3(LEN2 / 128, HID / 64, BATCH), 256>>>(zq, dtw, dtb, bufA);
    for (int i = 0; i < 2; i++) {
        k_conv<3, true, false><<<dim3(LEN2 / 128, HID / 64, BATCH), 256>>>(
            bufA, drw1 + (size_t)i * HID * HID * 3, drb1 + i * HID, nullptr, bufB,
            HID, HID, LEN2);
        k_conv<1, true, true><<<dim3(LEN2 / 128, HID / 64, BATCH), 256>>>(
            bufB, drw2 + (size_t)i * HID * HID, drb2 + i * HID, bufA, bufA,
            HID, HID, LEN2);
    }
    k_decfinal<<<dim3(LEN2 / 256, BATCH), 256>>>(bufA, dfw, dfb, dvec);

    // ---------------- output projection + scalars ----------------
    k_outproj<<<NITEMS / 64, 256>>>(dvec, opw, opb, out);
    k_final<<<1, 1>>>(scal, out, out_size);
}

// round 13
// speedup vs baseline: 1.4137x; 1.0344x over previous
#include <cuda_runtime.h>
#include <math.h>

#define BATCH   128
#define NITEMS  8192
#define HID     256
#define LAT     64
#define LEN1    4096
#define LEN2    8192
#define NEMB    512
#define NQ      4
#define MROWS   524288
#define VQBLOCKS 2048

// ---------------- scratch ----------------
__device__ float g_bufA[268435456];
__device__ float g_bufB[268435456];
__device__ float g_res [33554432];
__device__ float g_zq  [33554432];
__device__ float g_dvec[BATCH * NITEMS];
__device__ float g_counts[NEMB];
__device__ float g_scal[2];
__device__ float g_bsums[VQBLOCKS];
__device__ unsigned int g_xmax[8];
__device__ float g_Cval[8][256];

// grid-accumulator MAC (R11 proven): A stays on/near the 2^k grid of C;
// d = t2 - A exact (Sterbenz), e = full grid-quantization error. 4 ops/MAC.
#define GMAC(A, E, W, X) do {                                     \
    float _t2 = __fmaf_rn((W), (X), (A));                         \
    float _d  = __fsub_rn(_t2, (A));                              \
    float _e  = __fmaf_rn((W), (X), -_d);                         \
    (E) = __fadd_rn((E), _e);                                     \
    (A) = _t2;                                                    \
} while (0)

// per-output-channel grid constant: C = 2^(ilogb(L1(w)*xmax)+3)
__global__ void k_makeC(const float* __restrict__ wt, int CO, int CIK, int slot)
{
    int co = threadIdx.x;
    if (co >= CO) return;
    float l1 = 0.f;
    const float* w = wt + (size_t)co * CIK;
    for (int i = 0; i < CIK; i++) l1 += fabsf(w[i]);
    float xm = __uint_as_float(g_xmax[slot]);
    float B = l1 * xm;
    float C = 1.0f;
    if (B > 0.f) C = ldexpf(1.0f, ilogbf(B) + 3);
    g_Cval[slot][co] = C;
}

// warp+block max -> atomicMax (values >= 0 so uint order == float order)
__device__ __forceinline__ void blockmax_commit(float m, int slot)
{
    for (int off = 16; off > 0; off >>= 1)
        m = fmaxf(m, __shfl_xor_sync(0xffffffffu, m, off));
    if ((threadIdx.x & 31) == 0)
        atomicMax(&g_xmax[slot], __float_as_uint(m));
}

// =================================================================
// encoder conv1 (fp64-exact, tiny) + fused output max (slot 0)
// =================================================================
__global__ void __launch_bounds__(128) k_enc_conv1(
    const int* __restrict__ uid, const float* __restrict__ mat,
    const float* __restrict__ w, const float* __restrict__ bias,
    float* __restrict__ out)
{
    __shared__ float s_in[258];
    __shared__ float s_w[HID * 4];
    const int b  = blockIdx.y;
    const int l0 = blockIdx.x * 128;
    const int tx = threadIdx.x;
    const float* row = mat + (size_t)uid[b] * NITEMS;
    for (int i = tx; i < 258; i += 128) {
        int g = 2 * l0 - 1 + i;
        s_in[i] = (g >= 0 && g < NITEMS) ? row[g] : 0.f;
    }
    for (int i = tx; i < HID * 4; i += 128) s_w[i] = w[i];
    __syncthreads();
    const double x0 = s_in[2 * tx + 0], x1 = s_in[2 * tx + 1];
    const double x2 = s_in[2 * tx + 2], x3 = s_in[2 * tx + 3];
    const int l = l0 + tx;
    float m = 0.f;
    for (int co = 0; co < HID; co++) {
        double a = 0.0;
        a = fma((double)s_w[co * 4 + 0], x0, a);
        a = fma((double)s_w[co * 4 + 1], x1, a);
        a = fma((double)s_w[co * 4 + 2], x2, a);
        a = fma((double)s_w[co * 4 + 3], x3, a);
        float v = fmaxf(__fadd_rn((float)a, bias[co]), 0.f);
        m = fmaxf(m, v);
        out[((size_t)b * HID + co) * LEN1 + l] = v;
    }
    blockmax_commit(m, 0);
}

// =================================================================
// encoder conv1d, grid-accumulator exact (4 ops/MAC), retiled:
// Tile 64co x 128l, 256 thr, per-thread 4co x 8l. Per-output (ci,k)
// order identical to R11 -> bit-identical z_e.
// =================================================================
template <int K, bool RELU, bool ADDRES, int OUTSLOT>
__global__ void __launch_bounds__(256) k_convgrid(
    const float* __restrict__ in, const float* __restrict__ wt,
    const float* __restrict__ bias, const float* __restrict__ res,
    float* __restrict__ out, int CO, int CI, int L, int slot)
{
    constexpr int PAD = (K - 1) / 2;
    constexpr int LT = 128, COT = 64, CIC = 16;
    constexpr int LW = LT + 2 * PAD;
    __shared__ float s_in[CIC][LW];
    __shared__ float s_w[CIC][K][COT];

    const int b   = blockIdx.z;
    const int co0 = blockIdx.y * COT;
    const int l0  = blockIdx.x * LT;
    const int tid = threadIdx.x;
    const int lq = tid & 15, cq = tid >> 4;
    const int ls = lq * 8, cs = cq * 4;

    float Cc[4];
#pragma unroll
    for (int i = 0; i < 4; i++) Cc[i] = g_Cval[slot][co0 + cs + i];

    float A[4][8], E[4][8];
#pragma unroll
    for (int i = 0; i < 4; i++)
#pragma unroll
        for (int j = 0; j < 8; j++) { A[i][j] = Cc[i]; E[i][j] = 0.f; }

    for (int ci0 = 0; ci0 < CI; ci0 += CIC) {
        for (int idx = tid; idx < CIC * LW; idx += 256) {
            int ci = idx / LW, x = idx % LW;
            int l = l0 - PAD + x;
            float v = 0.f;
            if (l >= 0 && l < L) v = in[((size_t)b * CI + ci0 + ci) * L + l];
            s_in[ci][x] = v;
        }
        for (int idx = tid; idx < CIC * K * COT; idx += 256) {
            int co = idx % COT;
            int k  = (idx / COT) % K;
            int ci = idx / (COT * K);
            s_w[ci][k][co] = wt[((size_t)(co0 + co) * CI + ci0 + ci) * K + k];
        }
        __syncthreads();
#pragma unroll 2
        for (int ci = 0; ci < CIC; ci++) {
            float x[8 + K - 1];
#pragma unroll
            for (int t = 0; t < 8 + K - 1; t++) x[t] = s_in[ci][ls + t];
#pragma unroll
            for (int k = 0; k < K; k++) {
                float4 w4 = *reinterpret_cast<const float4*>(&s_w[ci][k][cs]);
                float wv[4] = {w4.x, w4.y, w4.z, w4.w};
#pragma unroll
                for (int i = 0; i < 4; i++)
#pragma unroll
                    for (int j = 0; j < 8; j++)
                        GMAC(A[i][j], E[i][j], wv[i], x[j + k]);
            }
        }
        __syncthreads();
    }
    float m = 0.f;
#pragma unroll
    for (int i = 0; i < 4; i++) {
        const int co = co0 + cs + i;
        const float bv = bias[co];
        const size_t o = ((size_t)b * CO + co) * L + l0 + ls;
        float v[8];
#pragma unroll
        for (int j = 0; j < 8; j++) {
            float hi = __fsub_rn(A[i][j], Cc[i]);       // exact
            v[j] = __fadd_rn(__fadd_rn(hi, E[i][j]), bv);
        }
        if (ADDRES) {
            float4 r0 = *reinterpret_cast<const float4*>(&res[o]);
            float4 r1 = *reinterpret_cast<const float4*>(&res[o + 4]);
            v[0] = __fadd_rn(v[0], r0.x); v[1] = __fadd_rn(v[1], r0.y);
            v[2] = __fadd_rn(v[2], r0.z); v[3] = __fadd_rn(v[3], r0.w);
            v[4] = __fadd_rn(v[4], r1.x); v[5] = __fadd_rn(v[5], r1.y);
            v[6] = __fadd_rn(v[6], r1.z); v[7] = __fadd_rn(v[7], r1.w);
        }
        if (RELU) {
#pragma unroll
            for (int j = 0; j < 8; j++) v[j] = fmaxf(v[j], 0.f);
        }
        if (OUTSLOT >= 0) {
#pragma unroll
            for (int j = 0; j < 8; j++) m = fmaxf(m, v[j]);
        }
        float4 o0 = {v[0], v[1], v[2], v[3]};
        float4 o1 = {v[4], v[5], v[6], v[7]};
        *reinterpret_cast<float4*>(&out[o])     = o0;
        *reinterpret_cast<float4*>(&out[o + 4]) = o1;
    }
    if (OUTSLOT >= 0) blockmax_commit(m, OUTSLOT);
}

// =================================================================
// decoder conv1d (fp32 scalar), K in {1,3}
// =================================================================
template <int K, bool RELU, bool ADDRES>
__global__ void __launch_bounds__(256) k_conv(
    const float* __restrict__ in, const float* __restrict__ wt,
    const float* __restrict__ bias, const float* __restrict__ res,
    float* __restrict__ out, int CO, int CI, int L)
{
    constexpr int PAD = (K - 1) / 2;
    constexpr int LT = 128, COT = 64, CIC = 16;
    constexpr int LW = LT + 2 * PAD;
    __shared__ float s_in[CIC][LW];
    __shared__ float s_w[CIC][K][COT];

    const int b   = blockIdx.z;
    const int co0 = blockIdx.y * COT;
    const int l0  = blockIdx.x * LT;
    const int tid = threadIdx.x;
    const int lq = tid & 15, cq = tid >> 4;
    const int ls = lq * 8, cs = cq * 4;

    float acc[4][8];
#pragma unroll
    for (int i = 0; i < 4; i++)
#pragma unroll
        for (int j = 0; j < 8; j++) acc[i][j] = 0.f;

    for (int ci0 = 0; ci0 < CI; ci0 += CIC) {
        for (int idx = tid; idx < CIC * LW; idx += 256) {
            int ci = idx / LW, x = idx % LW;
            int l = l0 - PAD + x;
            float v = 0.f;
            if (l >= 0 && l < L) v = in[((size_t)b * CI + ci0 + ci) * L + l];
            s_in[ci][x] = v;
        }
        for (int idx = tid; idx < CIC * K * COT; idx += 256) {
            int co = idx % COT;
            int k  = (idx / COT) % K;
            int ci = idx / (COT * K);
            s_w[ci][k][co] = wt[((size_t)(co0 + co) * CI + ci0 + ci) * K + k];
        }
        __syncthreads();
#pragma unroll 4
        for (int ci = 0; ci < CIC; ci++) {
            float x[8 + K - 1];
#pragma unroll
            for (int t = 0; t < 8 + K - 1; t++) x[t] = s_in[ci][ls + t];
#pragma unroll
            for (int k = 0; k < K; k++) {
                float4 w4 = *reinterpret_cast<const float4*>(&s_w[ci][k][cs]);
                float wv[4] = {w4.x, w4.y, w4.z, w4.w};
#pragma unroll
                for (int i = 0; i < 4; i++)
#pragma unroll
                    for (int j = 0; j < 8; j++)
                        acc[i][j] = fmaf(wv[i], x[j + k], acc[i][j]);
            }
        }
        __syncthreads();
    }
#pragma unroll
    for (int i = 0; i < 4; i++) {
        const int co = co0 + cs + i;
        const float bv = bias[co];
        const size_t o = ((size_t)b * CO + co) * L + l0 + ls;
        float v[8];
#pragma unroll
        for (int j = 0; j < 8; j++) v[j] = __fadd_rn(acc[i][j], bv);
        if (ADDRES) {
            float4 r0 = *reinterpret_cast<const float4*>(&res[o]);
            float4 r1 = *reinterpret_cast<const float4*>(&res[o + 4]);
            v[0] = __fadd_rn(v[0], r0.x); v[1] = __fadd_rn(v[1], r0.y);
            v[2] = __fadd_rn(v[2], r0.z); v[3] = __fadd_rn(v[3], r0.w);
            v[4] = __fadd_rn(v[4], r1.x); v[5] = __fadd_rn(v[5], r1.y);
            v[6] = __fadd_rn(v[6], r1.z); v[7] = __fadd_rn(v[7], r1.w);
        }
        if (RELU) {
#pragma unroll
            for (int j = 0; j < 8; j++) v[j] = fmaxf(v[j], 0.f);
        }
        float4 o0 = {v[0], v[1], v[2], v[3]};
        float4 o1 = {v[4], v[5], v[6], v[7]};
        *reinterpret_cast<float4*>(&out[o])     = o0;
        *reinterpret_cast<float4*>(&out[o + 4]) = o1;
    }
}

// =================================================================
// VQ: single-pass fp32 screen + exact fp64 refine
// =================================================================
__global__ void __launch_bounds__(256) k_vq(
    const float* __restrict__ cb, float* __restrict__ resid,
    float* __restrict__ zq, float* __restrict__ counts,
    float* __restrict__ bsums)
{
    extern __shared__ float sm[];
    float* s_code = sm;
    float* s_cn   = sm + NEMB * LAT;
    const int tid = threadIdx.x;

    for (int idx = tid; idx < NEMB * LAT / 4; idx += 256)
        reinterpret_cast<float4*>(s_code)[idx] =
            reinterpret_cast<const float4*>(cb)[idx];
    __syncthreads();
    for (int e = tid; e < NEMB; e += 256) {
        const float* c = s_code + e * LAT;
        double s = 0.0;
#pragma unroll
        for (int j = 0; j < 64; j++) s = fma((double)c[j], (double)c[j], s);
        s_cn[e] = (float)s;
    }
    __syncthreads();

    const size_t m = (size_t)blockIdx.x * 256 + tid;
    float r[64];
    {
        const float4* g = reinterpret_cast<const float4*>(resid + m * 64);
        float4* rr = reinterpret_cast<float4*>(r);
#pragma unroll
        for (int t = 0; t < 16; t++) rr[t] = g[t];
    }
    double rn64 = 0.0;
#pragma unroll
    for (int j = 0; j < 64; j++) rn64 = fma((double)r[j], (double)r[j], rn64);
    const float rn = (float)rn64;

    float sabs = 0.f;
#pragma unroll
    for (int j = 0; j < 64; j++) sabs = __fadd_rn(sabs, fabsf(r[j]));

    const float margin = 4.8e-7f * rn + 6.4e-8f * sabs + 1e-8f;

    float best_ka = 3.4e38f;
    int   cand[16];
    int   nc = 0;
    bool  overflow = false;
    for (int e = 0; e < NEMB; e += 4) {
        const float4* c0 = reinterpret_cast<const float4*>(s_code + (e + 0) * LAT);
        const float4* c1 = reinterpret_cast<const float4*>(s_code + (e + 1) * LAT);
        const float4* c2 = reinterpret_cast<const float4*>(s_code + (e + 2) * LAT);
        const float4* c3 = reinterpret_cast<const float4*>(s_code + (e + 3) * LAT);
        float d0 = 0.f, d1 = 0.f, d2 = 0.f, d3 = 0.f;
#pragma unroll
        for (int t = 0; t < 16; t++) {
            float4 a0 = c0[t], a1 = c1[t], a2 = c2[t], a3 = c3[t];
            float x0 = r[t*4+0], x1 = r[t*4+1], x2 = r[t*4+2], x3 = r[t*4+3];
            d0 = fmaf(a0.x, x0, d0); d0 = fmaf(a0.y, x1, d0);
            d0 = fmaf(a0.z, x2, d0); d0 = fmaf(a0.w, x3, d0);
            d1 = fmaf(a1.x, x0, d1); d1 = fmaf(a1.y, x1, d1);
            d1 = fmaf(a1.z, x2, d1); d1 = fmaf(a1.w, x3, d1);
            d2 = fmaf(a2.x, x0, d2); d2 = fmaf(a2.y, x1, d2);
            d2 = fmaf(a2.z, x2, d2); d2 = fmaf(a2.w, x3, d2);
            d3 = fmaf(a3.x, x0, d3); d3 = fmaf(a3.y, x1, d3);
            d3 = fmaf(a3.z, x2, d3); d3 = fmaf(a3.w, x3, d3);
        }
        float ka[4];
        ka[0] = __fsub_rn(__fadd_rn(rn, s_cn[e + 0]), __fmul_rn(2.f, d0));
        ka[1] = __fsub_rn(__fadd_rn(rn, s_cn[e + 1]), __fmul_rn(2.f, d1));
        ka[2] = __fsub_rn(__fadd_rn(rn, s_cn[e + 2]), __fmul_rn(2.f, d2));
        ka[3] = __fsub_rn(__fadd_rn(rn, s_cn[e + 3]), __fmul_rn(2.f, d3));
#pragma unroll
        for (int i = 0; i < 4; i++) {
            if (ka[i] < best_ka) best_ka = ka[i];
            if (ka[i] <= best_ka + margin) {
                if (nc < 16) cand[nc++] = e + i;
                else overflow = true;
            }
        }
    }

    float best = 3.4e38f;
    int bi = 0;
    if (!overflow) {
        for (int ci = 0; ci < nc; ci++) {
            int e = cand[ci];
            const float* c = s_code + (size_t)e * LAT;
            double dd = 0.0;
#pragma unroll
            for (int j = 0; j < 64; j++)
                dd = fma((double)c[j], (double)r[j], dd);
            float dot = (float)dd;
            float dist = __fsub_rn(__fadd_rn(rn, s_cn[e]),
                                   __fmul_rn(2.f, dot));
            if (dist < best) { best = dist; bi = e; }
        }
    } else {
        for (int e = 0; e < NEMB; e++) {
            const float* c = s_code + (size_t)e * LAT;
            double dd = 0.0;
#pragma unroll
            for (int j = 0; j < 64; j++)
                dd = fma((double)c[j], (double)r[j], dd);
            float dot = (float)dd;
            float dist = __fsub_rn(__fadd_rn(rn, s_cn[e]),
                                   __fmul_rn(2.f, dot));
            if (dist < best) { best = dist; bi = e; }
        }
    }

    float sq = 0.f;
    {
        const float* c = s_code + bi * LAT;
        float4* rg = reinterpret_cast<float4*>(resid + m * 64);
        float4* zg = reinterpret_cast<float4*>(zq + m * 64);
#pragma unroll
        for (int t = 0; t < 16; t++) {
            float4 zv = zg[t];
            float q[4] = {c[t*4+0], c[t*4+1], c[t*4+2], c[t*4+3]};
            float rv[4] = {r[t*4+0], r[t*4+1], r[t*4+2], r[t*4+3]};
            float4 nr, nz;
            float o_r[4], o_z[4];
#pragma unroll
            for (int u = 0; u < 4; u++) {
                float d  = __fsub_rn(q[u], rv[u]);
                sq = __fadd_rn(sq, __fmul_rn(d, d));
                float qs = __fadd_rn(rv[u], d);
                o_r[u] = __fsub_rn(rv[u], qs);
                o_z[u] = __fadd_rn((&zv.x)[u], qs);
            }
            nr.x = o_r[0]; nr.y = o_r[1]; nr.z = o_r[2]; nr.w = o_r[3];
            nz.x = o_z[0]; nz.y = o_z[1]; nz.z = o_z[2]; nz.w = o_z[3];
            rg[t] = nr; zg[t] = nz;
        }
    }
    atomicAdd(&counts[bi], 1.f);

    __shared__ float red[256];
    red[tid] = sq;
    __syncthreads();
    for (int s = 128; s > 0; s >>= 1) {
        if (tid < s) red[tid] += red[tid + s];
        __syncthreads();
    }
    if (tid == 0) bsums[blockIdx.x] = red[0];
}

__global__ void k_perp(const float* __restrict__ bsums, float* __restrict__ counts,
                       float* __restrict__ scal)
{
    __shared__ float red[512];
    __shared__ float red2[512];
    const int t = threadIdx.x;
    float c = counts[t];
    float avg = c * (1.0f / (float)MROWS);
    red[t] = avg * logf(avg + 1e-10f);
    float s2 = 0.f;
    for (int i = t; i < VQBLOCKS; i += 512) s2 += bsums[i];
    red2[t] = s2;
    __syncthreads();
    for (int s = 256; s > 0; s >>= 1) {
        if (t < s) { red[t] += red[t + s]; red2[t] += red2[t + s]; }
        __syncthreads();
    }
    if (t == 0) {
        scal[1] += expf(-red[0]);
        scal[0] += red2[0];
    }
    counts[t] = 0.f;
}

// =================================================================
// decoder ConvTranspose1d(64->256, K=4, s2, p1) + relu (fp32 scalar)
// =================================================================
__global__ void __launch_bounds__(256) k_dect(
    const float* __restrict__ in, const float* __restrict__ wt,
    const float* __restrict__ bias, float* __restrict__ out)
{
    constexpr int OT = 128, COT = 64, CIC = 32;
    __shared__ float s_in[CIC][66];
    __shared__ float s_w[CIC][4][COT];
    const int b   = blockIdx.z;
    const int co0 = blockIdx.y * COT;
    const int o0  = blockIdx.x * OT;
    const int tid = threadIdx.x;
    const int lq = tid & 15, cq = tid >> 4;
    const int os = lq * 8, cs = cq * 4;
    const int lbase = o0 / 2 - 1;

    float acc[4][8];
#pragma unroll
    for (int i = 0; i < 4; i++)
#pragma unroll
        for (int j = 0; j < 8; j++) acc[i][j] = 0.f;

    for (int ci0 = 0; ci0 < LAT; ci0 += CIC) {
        for (int idx = tid; idx < CIC * 66; idx += 256) {
            int ci = idx / 66, x = idx % 66;
            int l = lbase + x;
            float v = 0.f;
            if (l >= 0 && l < LEN1) v = in[((size_t)b * LAT + ci0 + ci) * LEN1 + l];
            s_in[ci][x] = v;
        }
        for (int idx = tid; idx < CIC * 4 * COT; idx += 256) {
            int co = idx & 63;
            int k  = (idx >> 6) & 3;
            int ci = idx >> 8;
            s_w[ci][k][co] = wt[((size_t)(ci0 + ci) * HID + co0 + co) * 4 + k];
        }
        __syncthreads();
#pragma unroll 4
        for (int ci = 0; ci < CIC; ci++) {
            float x[6];
#pragma unroll
            for (int t = 0; t < 6; t++) x[t] = s_in[ci][(os >> 1) + t];
            float4 W0 = *reinterpret_cast<const float4*>(&s_w[ci][0][cs]);
            float4 W1 = *reinterpret_cast<const float4*>(&s_w[ci][1][cs]);
            float4 W2 = *reinterpret_cast<const float4*>(&s_w[ci][2][cs]);
            float4 W3 = *reinterpret_cast<const float4*>(&s_w[ci][3][cs]);
            float wa[4][4] = {{W0.x, W0.y, W0.z, W0.w},
                              {W1.x, W1.y, W1.z, W1.w},
                              {W2.x, W2.y, W2.z, W2.w},
                              {W3.x, W3.y, W3.z, W3.w}};
#pragma unroll
            for (int jj = 0; jj < 4; jj++) {
                float xe0 = x[jj], xe1 = x[jj + 1], xo2 = x[jj + 2];
#pragma unroll
                for (int i = 0; i < 4; i++) {
                    acc[i][2 * jj]     = fmaf(wa[1][i], xe1, fmaf(wa[3][i], xe0, acc[i][2 * jj]));
                    acc[i][2 * jj + 1] = fmaf(wa[0][i], xo2, fmaf(wa[2][i], xe1, acc[i][2 * jj + 1]));
                }
            }
        }
        __syncthreads();
    }
#pragma unroll
    for (int i = 0; i < 4; i++) {
        const int co = co0 + cs + i;
        const float bv = bias[co];
        const size_t o = ((size_t)b * HID + co) * LEN2 + o0 + os;
        float v[8];
#pragma unroll
        for (int j = 0; j < 8; j++) v[j] = fmaxf(__fadd_rn(acc[i][j], bv), 0.f);
        float4 q0 = {v[0], v[1], v[2], v[3]};
        float4 q1 = {v[4], v[5], v[6], v[7]};
        *reinterpret_cast<float4*>(&out[o])     = q0;
        *reinterpret_cast<float4*>(&out[o + 4]) = q1;
    }
}

// =================================================================
// decoder ConvTranspose1d(256->1, K=3, s1, p1) (fp32)
// =================================================================
__global__ void __launch_bounds__(256) k_decfinal(
    const float* __restrict__ in, const float* __restrict__ wt,
    const float* __restrict__ bias, float* __restrict__ out)
{
    __shared__ float s_w[HID * 3];
    __shared__ float s_in[32][258];
    const int b  = blockIdx.y;
    const int o0 = blockIdx.x * 256;
    const int tx = threadIdx.x;
    for (int i = tx; i < HID * 3; i += 256) s_w[i] = wt[i];
    float acc = 0.f;
    for (int cc = 0; cc < HID; cc += 32) {
        __syncthreads();
        for (int idx = tx; idx < 32 * 258; idx += 256) {
            int ci = idx / 258, x = idx % 258;
            int l = o0 - 1 + x;
            s_in[ci][x] = (l >= 0 && l < LEN2)
                        ? in[((size_t)b * HID + cc + ci) * LEN2 + l] : 0.f;
        }
        __syncthreads();
#pragma unroll 8
        for (int ci = 0; ci < 32; ci++) {
            acc = fmaf(s_w[(cc + ci) * 3 + 0], s_in[ci][tx + 2], acc);
            acc = fmaf(s_w[(cc + ci) * 3 + 1], s_in[ci][tx + 1], acc);
            acc = fmaf(s_w[(cc + ci) * 3 + 2], s_in[ci][tx + 0], acc);
        }
    }
    out[(size_t)b * LEN2 + o0 + tx] = __fadd_rn(acc, bias[0]);
}

// =================================================================
// out projection (fp32 scalar)
// =================================================================
__global__ void __launch_bounds__(256) k_outproj(
    const float* __restrict__ dv, const float* __restrict__ W,
    const float* __restrict__ bias, float* __restrict__ out)
{
    constexpr int KC = 32;
    __shared__ float s_d[KC][136];
    __shared__ float s_w[KC][68];
    const int j0  = blockIdx.x * 64;
    const int tid = threadIdx.x;
    const int bq = tid & 15, jq = tid >> 4;
    const int bs = bq * 8, js = jq * 4;
    float acc[8][4];
#pragma unroll
    for (int i = 0; i < 8; i++)
#pragma unroll
        for (int j = 0; j < 4; j++) acc[i][j] = 0.f;

    for (int k0 = 0; k0 < NITEMS; k0 += KC) {
        for (int idx = tid; idx < KC * 128; idx += 256) {
            int bb = idx >> 5, k = idx & 31;
            s_d[k][bb] = dv[(size_t)bb * NITEMS + k0 + k];
        }
        for (int idx = tid; idx < KC * 64; idx += 256) {
            int j = idx >> 5, k = idx & 31;
            s_w[k][j] = W[(size_t)(j0 + j) * NITEMS + k0 + k];
        }
        __syncthreads();
#pragma unroll
        for (int k = 0; k < KC; k++) {
            float4 w4 = *reinterpret_cast<const float4*>(&s_w[k][js]);
            float xb[8];
            *reinterpret_cast<float4*>(&xb[0]) = *reinterpret_cast<const float4*>(&s_d[k][bs]);
            *reinterpret_cast<float4*>(&xb[4]) = *reinterpret_cast<const float4*>(&s_d[k][bs + 4]);
            float wv[4] = {w4.x, w4.y, w4.z, w4.w};
#pragma unroll
            for (int i = 0; i < 8; i++)
#pragma unroll
                for (int j = 0; j < 4; j++)
                    acc[i][j] = fmaf(xb[i], wv[j], acc[i][j]);
        }
        __syncthreads();
    }
#pragma unroll
    for (int i = 0; i < 8; i++) {
#pragma unroll
        for (int j = 0; j < 4; j++)
            out[(size_t)(bs + i) * NITEMS + j0 + js + j] =
                __fadd_rn(acc[i][j], bias[j0 + js + j]);
    }
}

__global__ void k_final(const float* __restrict__ scal, float* __restrict__ out, int out_size)
{
    if (out_size >= BATCH * NITEMS + 2) {
        out[BATCH * NITEMS + 0] = 1.25f * scal[0] * (1.0f / 33554432.0f);
        out[BATCH * NITEMS + 1] = scal[1] * 0.25f;
    }
}

// =================================================================
extern "C" void kernel_launch(void* const* d_in, const int* in_sizes, int n_in,
                              void* d_out, int out_size)
{
    const int*   uid  = (const int*)  d_in[0];
    const float* mat  = (const float*)d_in[1];
    const float* ecw  = (const float*)d_in[2];
    const float* ecb  = (const float*)d_in[3];
    const float* erw1 = (const float*)d_in[4];
    const float* erb1 = (const float*)d_in[5];
    const float* erw2 = (const float*)d_in[6];
    const float* erb2 = (const float*)d_in[7];
    const float* efw  = (const float*)d_in[8];
    const float* efb  = (const float*)d_in[9];
    const float* cbs  = (const float*)d_in[10];
    const float* dtw  = (const float*)d_in[11];
    const float* dtb  = (const float*)d_in[12];
    const float* drw1 = (const float*)d_in[13];
    const float* drb1 = (const float*)d_in[14];
    const float* drw2 = (const float*)d_in[15];
    const float* drb2 = (const float*)d_in[16];
    const float* dfw  = (const float*)d_in[17];
    const float* dfb  = (const float*)d_in[18];
    const float* opw  = (const float*)d_in[19];
    const float* opb  = (const float*)d_in[20];
    float* out = (float*)d_out;

    float *bufA, *bufB, *resid, *zq, *dvec, *counts, *scal, *bsums;
    unsigned int* xmax;
    cudaGetSymbolAddress((void**)&bufA,   g_bufA);
    cudaGetSymbolAddress((void**)&bufB,   g_bufB);
    cudaGetSymbolAddress((void**)&resid,  g_res);
    cudaGetSymbolAddress((void**)&zq,     g_zq);
    cudaGetSymbolAddress((void**)&dvec,   g_dvec);
    cudaGetSymbolAddress((void**)&counts, g_counts);
    cudaGetSymbolAddress((void**)&scal,   g_scal);
    cudaGetSymbolAddress((void**)&bsums,  g_bsums);
    cudaGetSymbolAddress((void**)&xmax,   g_xmax);

    const int vq_smem = (NEMB * LAT + NEMB) * (int)sizeof(float);
    cudaFuncSetAttribute(k_vq, cudaFuncAttributeMaxDynamicSharedMemorySize, vq_smem);

    cudaMemsetAsync(zq, 0, (size_t)33554432 * sizeof(float), 0);
    cudaMemsetAsync(scal, 0, 2 * sizeof(float), 0);
    cudaMemsetAsync(counts, 0, NEMB * sizeof(float), 0);
    cudaMemsetAsync(xmax, 0, 8 * sizeof(unsigned int), 0);

    // ---------------- encoder (grid-accumulator exact, fused max) -------
    k_enc_conv1<<<dim3(LEN1 / 128, BATCH), 128>>>(uid, mat, ecw, ecb, bufA);

    k_makeC<<<1, 256>>>(erw1, HID, HID * 3, 0);
    k_convgrid<3, true, false, 1><<<dim3(LEN1 / 128, HID / 64, BATCH), 256>>>(
        bufA, erw1, erb1, nullptr, bufB, HID, HID, LEN1, 0);

    k_makeC<<<1, 256>>>(erw2, HID, HID * 1, 1);
    k_convgrid<1, true, true, 2><<<dim3(LEN1 / 128, HID / 64, BATCH), 256>>>(
        bufB, erw2, erb2, bufA, bufA, HID, HID, LEN1, 1);

    k_makeC<<<1, 256>>>(erw1 + (size_t)HID * HID * 3, HID, HID * 3, 2);
    k_convgrid<3, true, false, 3><<<dim3(LEN1 / 128, HID / 64, BATCH), 256>>>(
        bufA, erw1 + (size_t)HID * HID * 3, erb1 + HID, nullptr, bufB,
        HID, HID, LEN1, 2);

    k_makeC<<<1, 256>>>(erw2 + (size_t)HID * HID, HID, HID * 1, 3);
    k_convgrid<1, true, true, 4><<<dim3(LEN1 / 128, HID / 64, BATCH), 256>>>(
        bufB, erw2 + (size_t)HID * HID, erb2 + HID, bufA, bufA,
        HID, HID, LEN1, 3);

    k_makeC<<<1, 256>>>(efw, LAT, HID * 3, 4);
    k_convgrid<3, false, false, -1><<<dim3(LEN1 / 128, LAT / 64, BATCH), 256>>>(
        bufA, efw, efb, nullptr, resid, LAT, HID, LEN1, 4);

    // ---------------- residual VQ ----------------
    for (int q = 0; q < NQ; q++) {
        k_vq<<<VQBLOCKS, 256, vq_smem>>>(cbs + (size_t)q * NEMB * LAT,
                                         resid, zq, counts, bsums);
        k_perp<<<1, 512>>>(bsums, counts, scal);
    }

    // ---------------- decoder (fp32 scalar) ----------------
    k_dect<<<dim3(LEN2 / 128, HID / 64, BATCH), 256>>>(zq, dtw, dtb, bufA);
    for (int i = 0; i < 2; i++) {
        k_conv<3, true, false><<<dim3(LEN2 / 128, HID / 64, BATCH), 256>>>(
            bufA, drw1 + (size_t)i * HID * HID * 3, drb1 + i * HID, nullptr, bufB,
            HID, HID, LEN2);
        k_conv<1, true, true><<<dim3(LEN2 / 128, HID / 64, BATCH), 256>>>(
            bufB, drw2 + (size_t)i * HID * HID, drb2 + i * HID, bufA, bufA,
            HID, HID, LEN2);
    }
    k_decfinal<<<dim3(LEN2 / 256, BATCH), 256>>>(bufA, dfw, dfb, dvec);

    // ---------------- output projection + scalars ----------------
    k_outproj<<<NITEMS / 64, 256>>>(dvec, opw, opb, out);
    k_final<<<1, 1>>>(scal, out, out_size);
}